// round 8
// baseline (speedup 1.0000x reference)
#include <cuda_runtime.h>
#include <cuda_fp16.h>
#include <cstdint>

#define BB   512
#define NN   256
#define NVT  32
#define HS   128
#define G3   384
#define NZ   64

// ---------- device globals (no allocation allowed) ----------
// B fragments: [s(2)][nt(64)][k(2)][lane(32)][reg(2)][half(2)] bf16 = 64 KB
__device__ uint4 g_Bf4[4096];
// gi table, fp16, layout [c(3)][h(128)][t(32)] = 24 KB (b_hh baked into r,z)
__device__ uint4 g_giT4[1536];
// A fragments per batch: [mt(16)][k(2)][lane(32)][reg(4)] bf16x2 = 16 KB/batch
__device__ uint4 g_Af4[(size_t)BB * 1024];

__device__ __forceinline__ float tanh_fast(float x) {
    float y;
    asm("tanh.approx.f32 %0, %1;" : "=f"(y) : "f"(x));
    return y;
}
__device__ __forceinline__ float sigmoid_fast(float x) {
    return fmaf(tanh_fast(0.5f * x), 0.5f, 0.5f);
}
__device__ __forceinline__ uint32_t f2bf(float x) {   // rn bf16 bits
    uint32_t u = __float_as_uint(x);
    u += 0x7fff + ((u >> 16) & 1);
    return u >> 16;
}
__device__ __forceinline__ void mma_bf16(float* c, const uint32_t* a,
                                         uint32_t b0, uint32_t b1) {
    asm volatile(
        "mma.sync.aligned.m16n8k16.row.col.f32.bf16.bf16.f32 "
        "{%0,%1,%2,%3}, {%4,%5,%6,%7}, {%8,%9}, {%0,%1,%2,%3};"
        : "+f"(c[0]), "+f"(c[1]), "+f"(c[2]), "+f"(c[3])
        : "r"(a[0]), "r"(a[1]), "r"(a[2]), "r"(a[3]), "r"(b0), "r"(b1));
}

// ---------- fused kernel: blocks [0,512) histogram, [512,544) tables ----------
__global__ __launch_bounds__(256)
void dvae_hist_tables_kernel(const int* __restrict__ node_types,
                             const int* __restrict__ adj,
                             const float* __restrict__ W_ih,
                             const float* __restrict__ W_hh,
                             const float* __restrict__ b_ih,
                             const float* __restrict__ b_hh,
                             const float* __restrict__ Wg,
                             const float* __restrict__ bg,
                             const float* __restrict__ Wm) {
    __shared__ int   s_cnti[NVT * NN];
    __shared__ int   s_type[NN];
    __shared__ float s_tbl[HS];

    const int tid = threadIdx.x;

    if (blockIdx.x >= BB) {
        // ================= tables block =================
        const int t = blockIdx.x - BB;       // 0..31 (type = K index)
        if (tid < HS) {
            float x  = Wg[tid * NVT + t] + bg[tid];
            float sg = __fdividef(1.f, 1.f + __expf(-x));
            s_tbl[tid] = sg * Wm[tid * NVT + t];
        }
        __syncthreads();

        unsigned short* B = (unsigned short*)g_Bf4;
        auto storeB = [&](int j, float val) {
            int nt = j >> 3, nin = j & 7;
            int k = t >> 4, kk = t & 15;
            int tig = (kk & 7) >> 1, half = kk & 1, reg = kk >> 3;
            int lane = nin * 4 + tig;
            int base = (((nt * 2 + k) * 32 + lane) * 2 + reg) * 2 + half;
            uint32_t hb = f2bf(val);
            float lo = val - __uint_as_float(hb << 16);
            B[base]         = (unsigned short)hb;
            B[16384 + base] = (unsigned short)f2bf(lo);
        };

        for (int g = tid; g < G3; g += 256) {
            const float4* w4 = (const float4*)(W_hh + g * HS);
            const float4* t4 = (const float4*)s_tbl;
            float a0 = 0.f, a1 = 0.f, a2 = 0.f, a3 = 0.f;
            #pragma unroll
            for (int i = 0; i < 32; i += 4) {
                float4 w0 = w4[i], w1 = w4[i+1], w2 = w4[i+2], w3 = w4[i+3];
                float4 x0 = t4[i], x1 = t4[i+1], x2 = t4[i+2], x3 = t4[i+3];
                a0 += w0.x*x0.x + w0.y*x0.y + w0.z*x0.z + w0.w*x0.w;
                a1 += w1.x*x1.x + w1.y*x1.y + w1.z*x1.z + w1.w*x1.w;
                a2 += w2.x*x2.x + w2.y*x2.y + w2.z*x2.z + w2.w*x2.w;
                a3 += w3.x*x3.x + w3.y*x3.y + w3.z*x3.z + w3.w*x3.w;
            }
            float acc = (a0 + a1) + (a2 + a3);
            storeB((g & 127) * 4 + (g >> 7), acc);   // j = h*4 + c
            __half* GI = (__half*)g_giT4;
            int c = g >> 7, h = g & 127;
            float val = W_ih[g * NVT + t] + b_ih[g] + ((g < 256) ? b_hh[g] : 0.f);
            GI[(c * 128 + h) * 32 + t] = __float2half_rn(val);
        }
        if (tid < HS) storeB(tid * 4 + 3, s_tbl[tid]);   // tbl columns
        return;
    }

    // ================= histogram block (R5 proven body) =================
    const int b = blockIdx.x;
    s_type[tid] = node_types[b * NN + tid];
    for (int i = tid; i < NVT * NN; i += 256) s_cnti[i] = 0;
    __syncthreads();

    const int* arow = adj + (size_t)b * NN * NN + tid;
    #pragma unroll 1
    for (int u0 = 0; u0 < NN; u0 += 8) {
        int a0 = __ldg(arow + (u0 + 0) * NN);
        int a1 = __ldg(arow + (u0 + 1) * NN);
        int a2 = __ldg(arow + (u0 + 2) * NN);
        int a3 = __ldg(arow + (u0 + 3) * NN);
        int a4 = __ldg(arow + (u0 + 4) * NN);
        int a5 = __ldg(arow + (u0 + 5) * NN);
        int a6 = __ldg(arow + (u0 + 6) * NN);
        int a7 = __ldg(arow + (u0 + 7) * NN);
        s_cnti[s_type[u0 + 0] * NN + tid] += a0;
        s_cnti[s_type[u0 + 1] * NN + tid] += a1;
        s_cnti[s_type[u0 + 2] * NN + tid] += a2;
        s_cnti[s_type[u0 + 3] * NN + tid] += a3;
        s_cnti[s_type[u0 + 4] * NN + tid] += a4;
        s_cnti[s_type[u0 + 5] * NN + tid] += a5;
        s_cnti[s_type[u0 + 6] * NN + tid] += a6;
        s_cnti[s_type[u0 + 7] * NN + tid] += a7;
    }
    __syncthreads();

    // write A fragments: counts are exact in bf16 (<= 255)
    uint32_t* dst = (uint32_t*)g_Af4 + (size_t)b * 4096;
    for (int lin = tid; lin < 4096; lin += 256) {
        int reg  = lin & 3;
        int lane = (lin >> 2) & 31;
        int k    = (lin >> 7) & 1;
        int mt   = lin >> 8;
        int g    = lane >> 2, tig = lane & 3;
        int v    = mt * 16 + (reg & 1) * 8 + g;
        int t0   = k * 16 + (reg >> 1) * 8 + tig * 2;
        uint32_t u0 = __float_as_uint((float)s_cnti[t0 * NN + v]) >> 16;
        uint32_t u1 = __float_as_uint((float)s_cnti[(t0 + 1) * NN + v]) >> 16;
        dst[lin] = u0 | (u1 << 16);
    }
}

// ---------- main kernel: bf16 mma GEMM + GRU + heads (R5 proven + tanh z) ----
// smem: sB 64K + pgi 24K + pbhn 512 + spart 4096 + phg 512 = 93.0 KB
#define SMEM_DYN (65536 + 24576 + 512 + 4096 + 512)

__global__ __launch_bounds__(256, 2)
void dvae_main_kernel(const int* __restrict__ node_types,
                      const float* __restrict__ b_hh,
                      const float* __restrict__ W1, const float* __restrict__ b1,
                      const float* __restrict__ W2, const float* __restrict__ b2,
                      float* __restrict__ out) {
    extern __shared__ char smem[];
    uint32_t* sB    = (uint32_t*)smem;                  // 16384 u32
    __half*   pgi   = (__half*)(smem + 65536);          // 12288 halves
    float*    pbhn  = (float*)(smem + 65536 + 24576);   // [128]
    float*    spart = pbhn + 128;                       // [8][128]
    float*    phg   = spart + 8 * 128;                  // [128]

    const int b    = blockIdx.x;
    const int tid  = threadIdx.x;
    const int wid  = tid >> 5;
    const int lane = tid & 31;

    // ---- stage B frags + gi (uint4 copies) ----
    {
        uint4* d = (uint4*)sB;
        for (int i = tid; i < 4096; i += 256) d[i] = g_Bf4[i];
        uint4* d2 = (uint4*)pgi;
        for (int i = tid; i < 1536; i += 256) d2[i] = g_giT4[i];
    }
    if (tid < 128) pbhn[tid] = b_hh[256 + tid];
    __syncthreads();

    // ---- A fragments: 2 m-tiles per warp, 2 k-steps ----
    uint4 areg[2][2];
    #pragma unroll
    for (int mt2 = 0; mt2 < 2; mt2++)
        #pragma unroll
        for (int k = 0; k < 2; k++)
            areg[mt2][k] = g_Af4[(size_t)b * 1024 +
                                 (((wid * 2 + mt2) * 2 + k) * 32 + lane)];

    const int g    = lane >> 2;
    const int tig  = lane & 3;
    const int odd  = tig & 1;
    const int hbit = tig >> 1;
    const int rowoff = g + (odd << 3);

    int   tv[2];
    bool  excl[2];
    #pragma unroll
    for (int mt2 = 0; mt2 < 2; mt2++) {
        int v = (wid * 2 + mt2) * 16 + rowoff;
        tv[mt2]   = node_types[b * NN + v];
        excl[mt2] = (v == 0) || (v == NN - 1);
    }

    // ---- GEMM + fused epilogue over 64 n-tiles ----
    #pragma unroll 2
    for (int nt = 0; nt < 64; nt++) {
        float cc[2][4] = {{0.f,0.f,0.f,0.f},{0.f,0.f,0.f,0.f}};
        #pragma unroll
        for (int s = 0; s < 2; s++)
            #pragma unroll
            for (int k = 0; k < 2; k++) {
                uint2 bb = *(const uint2*)(sB +
                    (((s * 64 + nt) * 2 + k) * 32 + lane) * 2);
                mma_bf16(cc[0], (const uint32_t*)&areg[0][k], bb.x, bb.y);
                mma_bf16(cc[1], (const uint32_t*)&areg[1][k], bb.x, bb.y);
            }

        const int h = nt * 2 + hbit;
        const float bhn = pbhn[h];
        float acc = 0.f;
        #pragma unroll
        for (int mt2 = 0; mt2 < 2; mt2++) {
            float* c = cc[mt2];
            // exchange between (r,z) lanes and (n,tb) lanes
            float r1 = __shfl_xor_sync(0xffffffffu, odd ? c[0] : c[2], 1);
            float r2 = __shfl_xor_sync(0xffffffffu, odd ? c[1] : c[3], 1);
            float rin  = odd ? r1 : c[0];
            float zin  = odd ? r2 : c[1];
            float nin  = odd ? c[2] : r1;
            float hpre = odd ? c[3] : r2;
            int ti = tv[mt2];
            float gi_r = __half2float(pgi[(      h) * 32 + ti]);
            float gi_z = __half2float(pgi[(128 + h) * 32 + ti]);
            float gi_n = __half2float(pgi[(256 + h) * 32 + ti]);
            float r  = sigmoid_fast(gi_r + rin);
            float z  = sigmoid_fast(gi_z + zin);
            float nn = tanh_fast(gi_n + r * (nin + bhn));
            float Hv = (1.f - z) * nn + z * hpre;
            if (!excl[mt2]) acc += Hv;
        }
        // reduce the 16 lanes sharing this h (masks avoid bit 1<<1)
        acc += __shfl_xor_sync(0xffffffffu, acc, 1);
        acc += __shfl_xor_sync(0xffffffffu, acc, 4);
        acc += __shfl_xor_sync(0xffffffffu, acc, 8);
        acc += __shfl_xor_sync(0xffffffffu, acc, 16);
        if ((lane & ~2u) == 0)            // lanes 0 (h even) and 2 (h odd)
            spart[wid * 128 + nt * 2 + (lane >> 1)] = acc;
    }
    __syncthreads();

    // ---- reduce partials, heads ----
    if (tid < HS) {
        float s = 0.f;
        #pragma unroll
        for (int w = 0; w < 8; w++) s += spart[w * 128 + tid];
        phg[tid] = s;
    }
    __syncthreads();

    if (tid < 2 * NZ) {
        const int j = tid & (NZ - 1);
        const float* W  = (tid < NZ) ? W1 : W2;
        const float* bv = (tid < NZ) ? b1 : b2;
        float a0 = bv[j], a1 = 0.f, a2 = 0.f, a3 = 0.f;
        #pragma unroll
        for (int h = 0; h < HS; h += 4) {
            a0 += phg[h + 0] * W[j * HS + h + 0];
            a1 += phg[h + 1] * W[j * HS + h + 1];
            a2 += phg[h + 2] * W[j * HS + h + 2];
            a3 += phg[h + 3] * W[j * HS + h + 3];
        }
        out[((tid < NZ) ? 0 : BB * NZ) + b * NZ + j] = (a0 + a1) + (a2 + a3);
    }
}

// ---------- launch ----------
extern "C" void kernel_launch(void* const* d_in, const int* in_sizes, int n_in,
                              void* d_out, int out_size) {
    const int*   node_types = (const int*)  d_in[0];
    const int*   adj        = (const int*)  d_in[1];
    const float* W_ih       = (const float*)d_in[2];
    const float* W_hh       = (const float*)d_in[3];
    const float* b_ih       = (const float*)d_in[4];
    const float* b_hh       = (const float*)d_in[5];
    const float* Wg         = (const float*)d_in[6];
    const float* bg         = (const float*)d_in[7];
    const float* Wm         = (const float*)d_in[8];
    const float* W1         = (const float*)d_in[9];
    const float* b1         = (const float*)d_in[10];
    const float* W2         = (const float*)d_in[11];
    const float* b2         = (const float*)d_in[12];
    float* out = (float*)d_out;

    cudaFuncSetAttribute(dvae_main_kernel,
                         cudaFuncAttributeMaxDynamicSharedMemorySize, SMEM_DYN);

    dvae_hist_tables_kernel<<<BB + NVT, 256>>>(node_types, adj,
                                               W_ih, W_hh, b_ih, b_hh,
                                               Wg, bg, Wm);
    dvae_main_kernel<<<BB, 256, SMEM_DYN>>>(node_types, b_hh,
                                            W1, b1, W2, b2, out);
}

// round 9
// speedup vs baseline: 1.6194x; 1.6194x over previous
#include <cuda_runtime.h>
#include <cuda_fp16.h>
#include <cstdint>

#define BB   512
#define NN   256
#define NVT  32
#define HS   128
#define G3   384
#define NZ   64

// ---------- device globals (no allocation allowed) ----------
// B fragments: [s(2)][nt(64)][k(2)][lane(32)][reg(2)][half(2)] bf16 = 64 KB
__device__ uint4 g_Bf4[4096];
// gi table, fp16, layout [c(3)][h(128)][t(32)] = 24 KB (b_hh baked into r,z)
__device__ uint4 g_giT4[1536];
// A fragments per batch: [mt(16)][k(2)][lane(32)][reg(4)] bf16x2 = 16 KB/batch
__device__ uint4 g_Af4[(size_t)BB * 1024];

__device__ __forceinline__ float tanh_fast(float x) {
    float y;
    asm("tanh.approx.f32 %0, %1;" : "=f"(y) : "f"(x));
    return y;
}
__device__ __forceinline__ float sigmoid_fast(float x) {
    return fmaf(tanh_fast(0.5f * x), 0.5f, 0.5f);
}
__device__ __forceinline__ uint32_t f2bf(float x) {   // rn bf16 bits
    uint32_t u = __float_as_uint(x);
    u += 0x7fff + ((u >> 16) & 1);
    return u >> 16;
}
__device__ __forceinline__ void mma_bf16(float* c, const uint32_t* a,
                                         uint32_t b0, uint32_t b1) {
    asm volatile(
        "mma.sync.aligned.m16n8k16.row.col.f32.bf16.bf16.f32 "
        "{%0,%1,%2,%3}, {%4,%5,%6,%7}, {%8,%9}, {%0,%1,%2,%3};"
        : "+f"(c[0]), "+f"(c[1]), "+f"(c[2]), "+f"(c[3])
        : "r"(a[0]), "r"(a[1]), "r"(a[2]), "r"(a[3]), "r"(b0), "r"(b1));
}

// ---------- fused kernel: blocks [0,512) histogram, [512,544) tables --------
// __launch_bounds__(256, 5): cap regs ~51 so the HIST path keeps 5 CTAs/SM
// residency (the tables branch may spill; it's 32 trivial blocks).
__global__ __launch_bounds__(256, 5)
void dvae_hist_tables_kernel(const int* __restrict__ node_types,
                             const int* __restrict__ adj,
                             const float* __restrict__ W_ih,
                             const float* __restrict__ W_hh,
                             const float* __restrict__ b_ih,
                             const float* __restrict__ b_hh,
                             const float* __restrict__ Wg,
                             const float* __restrict__ bg,
                             const float* __restrict__ Wm) {
    __shared__ int   s_cnti[NVT * NN];
    __shared__ int   s_type[NN];
    __shared__ float s_tbl[HS];

    const int tid = threadIdx.x;

    if (blockIdx.x >= BB) {
        // ================= tables block =================
        const int t = blockIdx.x - BB;       // 0..31 (type = K index)
        if (tid < HS) {
            float x  = Wg[tid * NVT + t] + bg[tid];
            float sg = __fdividef(1.f, 1.f + __expf(-x));
            s_tbl[tid] = sg * Wm[tid * NVT + t];
        }
        __syncthreads();

        unsigned short* B = (unsigned short*)g_Bf4;
        auto storeB = [&](int j, float val) {
            int nt = j >> 3, nin = j & 7;
            int k = t >> 4, kk = t & 15;
            int tig = (kk & 7) >> 1, half = kk & 1, reg = kk >> 3;
            int lane = nin * 4 + tig;
            int base = (((nt * 2 + k) * 32 + lane) * 2 + reg) * 2 + half;
            uint32_t hb = f2bf(val);
            float lo = val - __uint_as_float(hb << 16);
            B[base]         = (unsigned short)hb;
            B[16384 + base] = (unsigned short)f2bf(lo);
        };

        for (int g = tid; g < G3; g += 256) {
            const float2* w2 = (const float2*)(W_hh + g * HS);
            const float2* t2 = (const float2*)s_tbl;
            float a0 = 0.f, a1 = 0.f;
            #pragma unroll 8
            for (int i = 0; i < 64; i += 2) {
                float2 w0 = w2[i], w1 = w2[i + 1];
                float2 x0 = t2[i], x1 = t2[i + 1];
                a0 += w0.x * x0.x + w0.y * x0.y;
                a1 += w1.x * x1.x + w1.y * x1.y;
            }
            float acc = a0 + a1;
            storeB((g & 127) * 4 + (g >> 7), acc);   // j = h*4 + c
            __half* GI = (__half*)g_giT4;
            int c = g >> 7, h = g & 127;
            float val = W_ih[g * NVT + t] + b_ih[g] + ((g < 256) ? b_hh[g] : 0.f);
            GI[(c * 128 + h) * 32 + t] = __float2half_rn(val);
        }
        if (tid < HS) storeB(tid * 4 + 3, s_tbl[tid]);   // tbl columns
        return;
    }

    // ================= histogram block (R5 proven body) =================
    const int b = blockIdx.x;
    s_type[tid] = node_types[b * NN + tid];
    for (int i = tid; i < NVT * NN; i += 256) s_cnti[i] = 0;
    __syncthreads();

    const int* arow = adj + (size_t)b * NN * NN + tid;
    #pragma unroll 1
    for (int u0 = 0; u0 < NN; u0 += 8) {
        int a0 = __ldg(arow + (u0 + 0) * NN);
        int a1 = __ldg(arow + (u0 + 1) * NN);
        int a2 = __ldg(arow + (u0 + 2) * NN);
        int a3 = __ldg(arow + (u0 + 3) * NN);
        int a4 = __ldg(arow + (u0 + 4) * NN);
        int a5 = __ldg(arow + (u0 + 5) * NN);
        int a6 = __ldg(arow + (u0 + 6) * NN);
        int a7 = __ldg(arow + (u0 + 7) * NN);
        s_cnti[s_type[u0 + 0] * NN + tid] += a0;
        s_cnti[s_type[u0 + 1] * NN + tid] += a1;
        s_cnti[s_type[u0 + 2] * NN + tid] += a2;
        s_cnti[s_type[u0 + 3] * NN + tid] += a3;
        s_cnti[s_type[u0 + 4] * NN + tid] += a4;
        s_cnti[s_type[u0 + 5] * NN + tid] += a5;
        s_cnti[s_type[u0 + 6] * NN + tid] += a6;
        s_cnti[s_type[u0 + 7] * NN + tid] += a7;
    }
    __syncthreads();

    // write A fragments: counts are exact in bf16 (<= 255)
    uint32_t* dst = (uint32_t*)g_Af4 + (size_t)b * 4096;
    for (int lin = tid; lin < 4096; lin += 256) {
        int reg  = lin & 3;
        int lane = (lin >> 2) & 31;
        int k    = (lin >> 7) & 1;
        int mt   = lin >> 8;
        int g    = lane >> 2, tig = lane & 3;
        int v    = mt * 16 + (reg & 1) * 8 + g;
        int t0   = k * 16 + (reg >> 1) * 8 + tig * 2;
        uint32_t u0 = __float_as_uint((float)s_cnti[t0 * NN + v]) >> 16;
        uint32_t u1 = __float_as_uint((float)s_cnti[(t0 + 1) * NN + v]) >> 16;
        dst[lin] = u0 | (u1 << 16);
    }
}

// ---------- main kernel: bf16 mma GEMM + GRU + heads (R5 proven + tanh z) ----
// smem: sB 64K + pgi 24K + pbhn 512 + spart 4096 + phg 512 = 93.0 KB
#define SMEM_DYN (65536 + 24576 + 512 + 4096 + 512)

__global__ __launch_bounds__(256, 2)
void dvae_main_kernel(const int* __restrict__ node_types,
                      const float* __restrict__ b_hh,
                      const float* __restrict__ W1, const float* __restrict__ b1,
                      const float* __restrict__ W2, const float* __restrict__ b2,
                      float* __restrict__ out) {
    extern __shared__ char smem[];
    uint32_t* sB    = (uint32_t*)smem;                  // 16384 u32
    __half*   pgi   = (__half*)(smem + 65536);          // 12288 halves
    float*    pbhn  = (float*)(smem + 65536 + 24576);   // [128]
    float*    spart = pbhn + 128;                       // [8][128]
    float*    phg   = spart + 8 * 128;                  // [128]

    const int b    = blockIdx.x;
    const int tid  = threadIdx.x;
    const int wid  = tid >> 5;
    const int lane = tid & 31;

    // ---- stage B frags + gi (uint4 copies) ----
    {
        uint4* d = (uint4*)sB;
        for (int i = tid; i < 4096; i += 256) d[i] = g_Bf4[i];
        uint4* d2 = (uint4*)pgi;
        for (int i = tid; i < 1536; i += 256) d2[i] = g_giT4[i];
    }
    if (tid < 128) pbhn[tid] = b_hh[256 + tid];
    __syncthreads();

    // ---- A fragments: 2 m-tiles per warp, 2 k-steps ----
    uint4 areg[2][2];
    #pragma unroll
    for (int mt2 = 0; mt2 < 2; mt2++)
        #pragma unroll
        for (int k = 0; k < 2; k++)
            areg[mt2][k] = g_Af4[(size_t)b * 1024 +
                                 (((wid * 2 + mt2) * 2 + k) * 32 + lane)];

    const int g    = lane >> 2;
    const int tig  = lane & 3;
    const int odd  = tig & 1;
    const int hbit = tig >> 1;
    const int rowoff = g + (odd << 3);

    int   tv[2];
    bool  excl[2];
    #pragma unroll
    for (int mt2 = 0; mt2 < 2; mt2++) {
        int v = (wid * 2 + mt2) * 16 + rowoff;
        tv[mt2]   = node_types[b * NN + v];
        excl[mt2] = (v == 0) || (v == NN - 1);
    }

    // ---- GEMM + fused epilogue over 64 n-tiles ----
    #pragma unroll 2
    for (int nt = 0; nt < 64; nt++) {
        float cc[2][4] = {{0.f,0.f,0.f,0.f},{0.f,0.f,0.f,0.f}};
        #pragma unroll
        for (int s = 0; s < 2; s++)
            #pragma unroll
            for (int k = 0; k < 2; k++) {
                uint2 bb = *(const uint2*)(sB +
                    (((s * 64 + nt) * 2 + k) * 32 + lane) * 2);
                mma_bf16(cc[0], (const uint32_t*)&areg[0][k], bb.x, bb.y);
                mma_bf16(cc[1], (const uint32_t*)&areg[1][k], bb.x, bb.y);
            }

        const int h = nt * 2 + hbit;
        const float bhn = pbhn[h];
        float acc = 0.f;
        #pragma unroll
        for (int mt2 = 0; mt2 < 2; mt2++) {
            float* c = cc[mt2];
            // exchange between (r,z) lanes and (n,tb) lanes
            float r1 = __shfl_xor_sync(0xffffffffu, odd ? c[0] : c[2], 1);
            float r2 = __shfl_xor_sync(0xffffffffu, odd ? c[1] : c[3], 1);
            float rin  = odd ? r1 : c[0];
            float zin  = odd ? r2 : c[1];
            float nin  = odd ? c[2] : r1;
            float hpre = odd ? c[3] : r2;
            int ti = tv[mt2];
            float gi_r = __half2float(pgi[(      h) * 32 + ti]);
            float gi_z = __half2float(pgi[(128 + h) * 32 + ti]);
            float gi_n = __half2float(pgi[(256 + h) * 32 + ti]);
            float r  = sigmoid_fast(gi_r + rin);
            float z  = sigmoid_fast(gi_z + zin);
            float nn = tanh_fast(gi_n + r * (nin + bhn));
            float Hv = (1.f - z) * nn + z * hpre;
            if (!excl[mt2]) acc += Hv;
        }
        // reduce the 16 lanes sharing this h (masks avoid bit 1<<1)
        acc += __shfl_xor_sync(0xffffffffu, acc, 1);
        acc += __shfl_xor_sync(0xffffffffu, acc, 4);
        acc += __shfl_xor_sync(0xffffffffu, acc, 8);
        acc += __shfl_xor_sync(0xffffffffu, acc, 16);
        if ((lane & ~2u) == 0)            // lanes 0 (h even) and 2 (h odd)
            spart[wid * 128 + nt * 2 + (lane >> 1)] = acc;
    }
    __syncthreads();

    // ---- reduce partials, heads ----
    if (tid < HS) {
        float s = 0.f;
        #pragma unroll
        for (int w = 0; w < 8; w++) s += spart[w * 128 + tid];
        phg[tid] = s;
    }
    __syncthreads();

    if (tid < 2 * NZ) {
        const int j = tid & (NZ - 1);
        const float* W  = (tid < NZ) ? W1 : W2;
        const float* bv = (tid < NZ) ? b1 : b2;
        float a0 = bv[j], a1 = 0.f, a2 = 0.f, a3 = 0.f;
        #pragma unroll
        for (int h = 0; h < HS; h += 4) {
            a0 += phg[h + 0] * W[j * HS + h + 0];
            a1 += phg[h + 1] * W[j * HS + h + 1];
            a2 += phg[h + 2] * W[j * HS + h + 2];
            a3 += phg[h + 3] * W[j * HS + h + 3];
        }
        out[((tid < NZ) ? 0 : BB * NZ) + b * NZ + j] = (a0 + a1) + (a2 + a3);
    }
}

// ---------- launch ----------
extern "C" void kernel_launch(void* const* d_in, const int* in_sizes, int n_in,
                              void* d_out, int out_size) {
    const int*   node_types = (const int*)  d_in[0];
    const int*   adj        = (const int*)  d_in[1];
    const float* W_ih       = (const float*)d_in[2];
    const float* W_hh       = (const float*)d_in[3];
    const float* b_ih       = (const float*)d_in[4];
    const float* b_hh       = (const float*)d_in[5];
    const float* Wg         = (const float*)d_in[6];
    const float* bg         = (const float*)d_in[7];
    const float* Wm         = (const float*)d_in[8];
    const float* W1         = (const float*)d_in[9];
    const float* b1         = (const float*)d_in[10];
    const float* W2         = (const float*)d_in[11];
    const float* b2         = (const float*)d_in[12];
    float* out = (float*)d_out;

    cudaFuncSetAttribute(dvae_main_kernel,
                         cudaFuncAttributeMaxDynamicSharedMemorySize, SMEM_DYN);

    dvae_hist_tables_kernel<<<BB + NVT, 256>>>(node_types, adj,
                                               W_ih, W_hh, b_ih, b_hh,
                                               Wg, bg, Wm);
    dvae_main_kernel<<<BB, 256, SMEM_DYN>>>(node_types, b_hh,
                                            W1, b1, W2, b2, out);
}

// round 10
// speedup vs baseline: 1.7086x; 1.0551x over previous
#include <cuda_runtime.h>
#include <cuda_fp16.h>
#include <cstdint>

#define BB   512
#define NN   256
#define NVT  32
#define HS   128
#define G3   384
#define NZ   64

// ---------- device globals (no allocation allowed) ----------
// B fragments: [s(2)][nt(64)][lane(32)] x uint4 {k0r0,k0r1,k1r0,k1r1} = 64 KB
__device__ uint4 g_Bf4[4096];
// gi packed: [h(128)][t(32)] x 4 fp16 {gi_r, gi_z, gi_n, bhn_h} = 32 KB
__device__ uint4 g_gi4[2048];
// A fragments per batch: [mt(16)][k(2)][lane(32)][reg(4)] bf16x2 = 16 KB/batch
__device__ uint4 g_Af4[(size_t)BB * 1024];

__device__ __forceinline__ float tanh_fast(float x) {
    float y;
    asm("tanh.approx.f32 %0, %1;" : "=f"(y) : "f"(x));
    return y;
}
__device__ __forceinline__ float sigmoid_fast(float x) {
    return fmaf(tanh_fast(0.5f * x), 0.5f, 0.5f);
}
__device__ __forceinline__ uint32_t f2bf(float x) {   // rn bf16 bits
    uint32_t u = __float_as_uint(x);
    u += 0x7fff + ((u >> 16) & 1);
    return u >> 16;
}
__device__ __forceinline__ void mma_bf16(float* c, const uint32_t* a,
                                         uint32_t b0, uint32_t b1) {
    asm volatile(
        "mma.sync.aligned.m16n8k16.row.col.f32.bf16.bf16.f32 "
        "{%0,%1,%2,%3}, {%4,%5,%6,%7}, {%8,%9}, {%0,%1,%2,%3};"
        : "+f"(c[0]), "+f"(c[1]), "+f"(c[2]), "+f"(c[3])
        : "r"(a[0]), "r"(a[1]), "r"(a[2]), "r"(a[3]), "r"(b0), "r"(b1));
}

// ---------- fused kernel: blocks [0,512) histogram, [512,544) tables --------
__global__ __launch_bounds__(256, 5)
void dvae_hist_tables_kernel(const int* __restrict__ node_types,
                             const int* __restrict__ adj,
                             const float* __restrict__ W_ih,
                             const float* __restrict__ W_hh,
                             const float* __restrict__ b_ih,
                             const float* __restrict__ b_hh,
                             const float* __restrict__ Wg,
                             const float* __restrict__ bg,
                             const float* __restrict__ Wm) {
    __shared__ int   s_cnti[NVT * NN];
    __shared__ int   s_type[NN];
    __shared__ float s_tbl[HS];

    const int tid = threadIdx.x;

    if (blockIdx.x >= BB) {
        // ================= tables block =================
        const int t = blockIdx.x - BB;       // 0..31 (type = K index)
        if (tid < HS) {
            float x  = Wg[tid * NVT + t] + bg[tid];
            float sg = __fdividef(1.f, 1.f + __expf(-x));
            s_tbl[tid] = sg * Wm[tid * NVT + t];
        }
        __syncthreads();

        unsigned short* B = (unsigned short*)g_Bf4;
        auto storeB = [&](int j, float val) {
            int nt = j >> 3, nin = j & 7;
            int k = t >> 4, kk = t & 15;
            int tig = (kk & 7) >> 1, half = kk & 1, reg = kk >> 3;
            int lane = nin * 4 + tig;
            int base = ((nt * 32 + lane) * 8) + k * 4 + reg * 2 + half;
            uint32_t hb = f2bf(val);
            float lo = val - __uint_as_float(hb << 16);
            B[base]         = (unsigned short)hb;
            B[16384 + base] = (unsigned short)f2bf(lo);
        };

        for (int g = tid; g < G3; g += 256) {
            const float2* w2 = (const float2*)(W_hh + g * HS);
            const float2* t2 = (const float2*)s_tbl;
            float a0 = 0.f, a1 = 0.f;
            #pragma unroll 8
            for (int i = 0; i < 64; i += 2) {
                float2 w0 = w2[i], w1 = w2[i + 1];
                float2 x0 = t2[i], x1 = t2[i + 1];
                a0 += w0.x * x0.x + w0.y * x0.y;
                a1 += w1.x * x1.x + w1.y * x1.y;
            }
            float acc = a0 + a1;
            storeB((g & 127) * 4 + (g >> 7), acc);   // j = h*4 + c
            // gi packed: [h][t] {r,z,n,bhn}
            __half* GI = (__half*)g_gi4;
            int c = g >> 7, h = g & 127;
            float val = W_ih[g * NVT + t] + b_ih[g] + ((g < 256) ? b_hh[g] : 0.f);
            GI[(h * 32 + t) * 4 + c] = __float2half_rn(val);
        }
        if (tid < HS) {
            storeB(tid * 4 + 3, s_tbl[tid]);   // tbl columns
            __half* GI = (__half*)g_gi4;
            GI[(tid * 32 + t) * 4 + 3] = __float2half_rn(b_hh[256 + tid]);
        }
        return;
    }

    // ================= histogram block (R5 proven body) =================
    const int b = blockIdx.x;
    s_type[tid] = node_types[b * NN + tid];
    for (int i = tid; i < NVT * NN; i += 256) s_cnti[i] = 0;
    __syncthreads();

    const int* arow = adj + (size_t)b * NN * NN + tid;
    #pragma unroll 1
    for (int u0 = 0; u0 < NN; u0 += 8) {
        int a0 = __ldg(arow + (u0 + 0) * NN);
        int a1 = __ldg(arow + (u0 + 1) * NN);
        int a2 = __ldg(arow + (u0 + 2) * NN);
        int a3 = __ldg(arow + (u0 + 3) * NN);
        int a4 = __ldg(arow + (u0 + 4) * NN);
        int a5 = __ldg(arow + (u0 + 5) * NN);
        int a6 = __ldg(arow + (u0 + 6) * NN);
        int a7 = __ldg(arow + (u0 + 7) * NN);
        s_cnti[s_type[u0 + 0] * NN + tid] += a0;
        s_cnti[s_type[u0 + 1] * NN + tid] += a1;
        s_cnti[s_type[u0 + 2] * NN + tid] += a2;
        s_cnti[s_type[u0 + 3] * NN + tid] += a3;
        s_cnti[s_type[u0 + 4] * NN + tid] += a4;
        s_cnti[s_type[u0 + 5] * NN + tid] += a5;
        s_cnti[s_type[u0 + 6] * NN + tid] += a6;
        s_cnti[s_type[u0 + 7] * NN + tid] += a7;
    }
    __syncthreads();

    // write A fragments: counts are exact in bf16 (<= 255)
    uint32_t* dst = (uint32_t*)g_Af4 + (size_t)b * 4096;
    for (int lin = tid; lin < 4096; lin += 256) {
        int reg  = lin & 3;
        int lane = (lin >> 2) & 31;
        int k    = (lin >> 7) & 1;
        int mt   = lin >> 8;
        int g    = lane >> 2, tig = lane & 3;
        int v    = mt * 16 + (reg & 1) * 8 + g;
        int t0   = k * 16 + (reg >> 1) * 8 + tig * 2;
        uint32_t u0 = __float_as_uint((float)s_cnti[t0 * NN + v]) >> 16;
        uint32_t u1 = __float_as_uint((float)s_cnti[(t0 + 1) * NN + v]) >> 16;
        dst[lin] = u0 | (u1 << 16);
    }
}

// ---------- main kernel: 512 thr, 2 batches/CTA, shared B/gi tables ----------
// smem: sB 64K + gi4 32K + spart 8K + phg 1K = 105 KB -> 2 CTAs/SM (32 warps)
#define SMEM_DYN (65536 + 32768 + 8192 + 1024)

__global__ __launch_bounds__(512, 2)
void dvae_main_kernel(const int* __restrict__ node_types,
                      const float* __restrict__ W1, const float* __restrict__ b1,
                      const float* __restrict__ W2, const float* __restrict__ b2,
                      float* __restrict__ out) {
    extern __shared__ char smem[];
    uint4*  sB4   = (uint4*)smem;                       // [2][64][32] uint4
    __half* gi4   = (__half*)(smem + 65536);            // [128][32][4]
    float*  spart = (float*)(smem + 65536 + 32768);     // [2][8][128]
    float*  phg   = spart + 2 * 8 * 128;                // [2][128]

    const int tid  = threadIdx.x;
    const int wg   = tid >> 8;          // 0/1 -> which batch
    const int wid8 = (tid >> 5) & 7;    // warp within group
    const int lane = tid & 31;
    const int b    = blockIdx.x * 2 + wg;

    // ---- stage B frags + gi4 (uint4 copies, all 512 threads) ----
    for (int i = tid; i < 4096; i += 512) sB4[i] = g_Bf4[i];
    {
        uint4* d2 = (uint4*)gi4;
        for (int i = tid; i < 2048; i += 512) d2[i] = g_gi4[i];
    }
    __syncthreads();

    // ---- A fragments: 2 m-tiles per warp, 2 k-steps ----
    uint4 areg[2][2];
    #pragma unroll
    for (int mt2 = 0; mt2 < 2; mt2++)
        #pragma unroll
        for (int k = 0; k < 2; k++)
            areg[mt2][k] = g_Af4[(size_t)b * 1024 +
                                 (((wid8 * 2 + mt2) * 2 + k) * 32 + lane)];

    const int g    = lane >> 2;
    const int tig  = lane & 3;
    const int odd  = tig & 1;
    const int hbit = tig >> 1;
    const int rowoff = g + (odd << 3);

    int   tv[2];
    bool  excl[2];
    #pragma unroll
    for (int mt2 = 0; mt2 < 2; mt2++) {
        int v = (wid8 * 2 + mt2) * 16 + rowoff;
        tv[mt2]   = node_types[b * NN + v];
        excl[mt2] = (v == 0) || (v == NN - 1);
    }

    float* my_spart = spart + wg * 1024 + wid8 * 128;

    // ---- GEMM + fused epilogue over 64 n-tiles (unroll 1: stay <=64 regs) ----
    #pragma unroll 1
    for (int nt = 0; nt < 64; nt++) {
        float cc[2][4] = {{0.f,0.f,0.f,0.f},{0.f,0.f,0.f,0.f}};
        #pragma unroll
        for (int s = 0; s < 2; s++) {
            uint4 bb = sB4[(s * 64 + nt) * 32 + lane];   // LDS.128
            mma_bf16(cc[0], (const uint32_t*)&areg[0][0], bb.x, bb.y);
            mma_bf16(cc[1], (const uint32_t*)&areg[1][0], bb.x, bb.y);
            mma_bf16(cc[0], (const uint32_t*)&areg[0][1], bb.z, bb.w);
            mma_bf16(cc[1], (const uint32_t*)&areg[1][1], bb.z, bb.w);
        }

        const int h = nt * 2 + hbit;
        float acc = 0.f;
        #pragma unroll
        for (int mt2 = 0; mt2 < 2; mt2++) {
            float* c = cc[mt2];
            // exchange between (r,z) lanes and (n,tb) lanes
            float r1 = __shfl_xor_sync(0xffffffffu, odd ? c[0] : c[2], 1);
            float r2 = __shfl_xor_sync(0xffffffffu, odd ? c[1] : c[3], 1);
            float rin  = odd ? r1 : c[0];
            float zin  = odd ? r2 : c[1];
            float nin  = odd ? c[2] : r1;
            float hpre = odd ? c[3] : r2;
            // one LDS.64: {gi_r, gi_z, gi_n, bhn}
            uint2 gv = *(const uint2*)(gi4 + ((h * 32 + tv[mt2]) << 2));
            float2 f_rz = __half22float2(*(const __half2*)&gv.x);
            float2 f_nb = __half22float2(*(const __half2*)&gv.y);
            float r  = sigmoid_fast(f_rz.x + rin);
            float z  = sigmoid_fast(f_rz.y + zin);
            float nn = tanh_fast(f_nb.x + r * (nin + f_nb.y));
            float Hv = (1.f - z) * nn + z * hpre;
            if (!excl[mt2]) acc += Hv;
        }
        // reduce the 16 lanes sharing this h
        acc += __shfl_xor_sync(0xffffffffu, acc, 1);
        acc += __shfl_xor_sync(0xffffffffu, acc, 4);
        acc += __shfl_xor_sync(0xffffffffu, acc, 8);
        acc += __shfl_xor_sync(0xffffffffu, acc, 16);
        if ((lane & ~2u) == 0)            // lanes 0 (h even) and 2 (h odd)
            my_spart[nt * 2 + (lane >> 1)] = acc;
    }
    __syncthreads();

    // ---- reduce partials, heads (per warp-group / batch) ----
    const int wg_tid = tid & 255;
    if (wg_tid < HS) {
        const float* sp = spart + wg * 1024;
        float s = 0.f;
        #pragma unroll
        for (int w = 0; w < 8; w++) s += sp[w * 128 + wg_tid];
        phg[wg * 128 + wg_tid] = s;
    }
    __syncthreads();

    if (wg_tid < 2 * NZ) {
        const int j = wg_tid & (NZ - 1);
        const float* W  = (wg_tid < NZ) ? W1 : W2;
        const float* bv = (wg_tid < NZ) ? b1 : b2;
        const float* hgp = phg + wg * 128;
        float a0 = bv[j], a1 = 0.f, a2 = 0.f, a3 = 0.f;
        #pragma unroll
        for (int h = 0; h < HS; h += 4) {
            a0 += hgp[h + 0] * W[j * HS + h + 0];
            a1 += hgp[h + 1] * W[j * HS + h + 1];
            a2 += hgp[h + 2] * W[j * HS + h + 2];
            a3 += hgp[h + 3] * W[j * HS + h + 3];
        }
        out[((wg_tid < NZ) ? 0 : BB * NZ) + b * NZ + j] = (a0 + a1) + (a2 + a3);
    }
}

// ---------- launch ----------
extern "C" void kernel_launch(void* const* d_in, const int* in_sizes, int n_in,
                              void* d_out, int out_size) {
    const int*   node_types = (const int*)  d_in[0];
    const int*   adj        = (const int*)  d_in[1];
    const float* W_ih       = (const float*)d_in[2];
    const float* W_hh       = (const float*)d_in[3];
    const float* b_ih       = (const float*)d_in[4];
    const float* b_hh       = (const float*)d_in[5];
    const float* Wg         = (const float*)d_in[6];
    const float* bg         = (const float*)d_in[7];
    const float* Wm         = (const float*)d_in[8];
    const float* W1         = (const float*)d_in[9];
    const float* b1         = (const float*)d_in[10];
    const float* W2         = (const float*)d_in[11];
    const float* b2         = (const float*)d_in[12];
    float* out = (float*)d_out;

    cudaFuncSetAttribute(dvae_main_kernel,
                         cudaFuncAttributeMaxDynamicSharedMemorySize, SMEM_DYN);

    dvae_hist_tables_kernel<<<BB + NVT, 256>>>(node_types, adj,
                                               W_ih, W_hh, b_ih, b_hh,
                                               Wg, bg, Wm);
    dvae_main_kernel<<<BB / 2, 512, SMEM_DYN>>>(node_types,
                                                W1, b1, W2, b2, out);
}

// round 11
// speedup vs baseline: 2.0735x; 1.2136x over previous
#include <cuda_runtime.h>
#include <cuda_fp16.h>
#include <cstdint>

#define BB   512
#define NN   256
#define NVT  32
#define HS   128
#define G3   384
#define NZ   64

// ---------- device globals (no allocation allowed) ----------
// B fragments: [s(2)][nt(64)][lane(32)] x uint4 {k0r0,k0r1,k1r0,k1r1} = 64 KB
__device__ uint4 g_Bf4[4096];
// gi packed: [h(128)][t(32)] x 4 fp16 {gi_r, gi_z, gi_n, bhn_h} = 32 KB
__device__ uint4 g_gi4[2048];
// A fragments per batch: [mt(16)][k(2)][lane(32)][reg(4)] bf16x2 = 16 KB/batch
__device__ uint4 g_Af4[(size_t)BB * 1024];

__device__ __forceinline__ float tanh_fast(float x) {
    float y;
    asm("tanh.approx.f32 %0, %1;" : "=f"(y) : "f"(x));
    return y;
}
__device__ __forceinline__ float sigmoid_fast(float x) {
    return fmaf(tanh_fast(0.5f * x), 0.5f, 0.5f);
}
__device__ __forceinline__ uint32_t f2bf(float x) {   // rn bf16 bits
    uint32_t u = __float_as_uint(x);
    u += 0x7fff + ((u >> 16) & 1);
    return u >> 16;
}
__device__ __forceinline__ void mma_bf16(float* c, const uint32_t* a,
                                         uint32_t b0, uint32_t b1) {
    asm volatile(
        "mma.sync.aligned.m16n8k16.row.col.f32.bf16.bf16.f32 "
        "{%0,%1,%2,%3}, {%4,%5,%6,%7}, {%8,%9}, {%0,%1,%2,%3};"
        : "+f"(c[0]), "+f"(c[1]), "+f"(c[2]), "+f"(c[3])
        : "r"(a[0]), "r"(a[1]), "r"(a[2]), "r"(a[3]), "r"(b0), "r"(b1));
}

// ---------- fused kernel: blocks [0,512) histogram, [512,544) tables --------
__global__ __launch_bounds__(256, 5)
void dvae_hist_tables_kernel(const int* __restrict__ node_types,
                             const int* __restrict__ adj,
                             const float* __restrict__ W_ih,
                             const float* __restrict__ W_hh,
                             const float* __restrict__ b_ih,
                             const float* __restrict__ b_hh,
                             const float* __restrict__ Wg,
                             const float* __restrict__ bg,
                             const float* __restrict__ Wm) {
    // [grp(4)][t(32)][v4(64)] u32, 4 packed u8 counters each = 32 KB
    __shared__ uint32_t s_cnt32[4 * NVT * 64];
    __shared__ int      s_type[NN];
    __shared__ float    s_tbl[HS];

    const int tid = threadIdx.x;

    if (blockIdx.x >= BB) {
        // ================= tables block =================
        const int t = blockIdx.x - BB;       // 0..31 (type = K index)
        if (tid < HS) {
            float x  = Wg[tid * NVT + t] + bg[tid];
            float sg = __fdividef(1.f, 1.f + __expf(-x));
            s_tbl[tid] = sg * Wm[tid * NVT + t];
        }
        __syncthreads();

        unsigned short* B = (unsigned short*)g_Bf4;
        auto storeB = [&](int j, float val) {
            int nt = j >> 3, nin = j & 7;
            int k = t >> 4, kk = t & 15;
            int tig = (kk & 7) >> 1, half = kk & 1, reg = kk >> 3;
            int lane = nin * 4 + tig;
            int base = ((nt * 32 + lane) * 8) + k * 4 + reg * 2 + half;
            uint32_t hb = f2bf(val);
            float lo = val - __uint_as_float(hb << 16);
            B[base]         = (unsigned short)hb;
            B[16384 + base] = (unsigned short)f2bf(lo);
        };

        for (int g = tid; g < G3; g += 256) {
            const float2* w2 = (const float2*)(W_hh + g * HS);
            const float2* t2 = (const float2*)s_tbl;
            float a0 = 0.f, a1 = 0.f;
            #pragma unroll 8
            for (int i = 0; i < 64; i += 2) {
                float2 w0 = w2[i], w1 = w2[i + 1];
                float2 x0 = t2[i], x1 = t2[i + 1];
                a0 += w0.x * x0.x + w0.y * x0.y;
                a1 += w1.x * x1.x + w1.y * x1.y;
            }
            float acc = a0 + a1;
            storeB((g & 127) * 4 + (g >> 7), acc);   // j = h*4 + c
            // gi packed: [h][t] {r,z,n,bhn}
            __half* GI = (__half*)g_gi4;
            int c = g >> 7, h = g & 127;
            float val = W_ih[g * NVT + t] + b_ih[g] + ((g < 256) ? b_hh[g] : 0.f);
            GI[(h * 32 + t) * 4 + c] = __float2half_rn(val);
        }
        if (tid < HS) {
            storeB(tid * 4 + 3, s_tbl[tid]);   // tbl columns
            __half* GI = (__half*)g_gi4;
            GI[(tid * 32 + t) * 4 + 3] = __float2half_rn(b_hh[256 + tid]);
        }
        return;
    }

    // ================= histogram block (packed-byte counters) =================
    const int b = blockIdx.x;
    s_type[tid] = node_types[b * NN + tid];
    for (int i = tid; i < 4 * NVT * 64; i += 256) s_cnt32[i] = 0;
    __syncthreads();

    {
        const int vg    = tid & 63;      // which v-quad (v = 4*vg .. 4*vg+3)
        const int ug    = tid >> 6;      // u-group 0..3 (private partials)
        const int ubase = ug * 64;
        // int4 view of adj rows: one int4 = 4 consecutive v of one u row
        const int4* arow =
            (const int4*)(adj + ((size_t)b * NN + ubase) * NN) + vg;
        uint32_t* cbase = s_cnt32 + ug * (NVT * 64) + vg;

        #pragma unroll 1
        for (int u = 0; u < 64; u += 4) {
            int4 a0 = __ldg(arow + (u + 0) * 64);
            int4 a1 = __ldg(arow + (u + 1) * 64);
            int4 a2 = __ldg(arow + (u + 2) * 64);
            int4 a3 = __ldg(arow + (u + 3) * 64);
            int t0 = s_type[ubase + u + 0];
            int t1 = s_type[ubase + u + 1];
            int t2 = s_type[ubase + u + 2];
            int t3 = s_type[ubase + u + 3];
            uint32_t p0 = (uint32_t)a0.x | ((uint32_t)a0.y << 8) |
                          ((uint32_t)a0.z << 16) | ((uint32_t)a0.w << 24);
            uint32_t p1 = (uint32_t)a1.x | ((uint32_t)a1.y << 8) |
                          ((uint32_t)a1.z << 16) | ((uint32_t)a1.w << 24);
            uint32_t p2 = (uint32_t)a2.x | ((uint32_t)a2.y << 8) |
                          ((uint32_t)a2.z << 16) | ((uint32_t)a2.w << 24);
            uint32_t p3 = (uint32_t)a3.x | ((uint32_t)a3.y << 8) |
                          ((uint32_t)a3.z << 16) | ((uint32_t)a3.w << 24);
            cbase[t0 * 64] += p0;     // 4 byte-counters per RMW
            cbase[t1 * 64] += p1;
            cbase[t2 * 64] += p2;
            cbase[t3 * 64] += p3;
        }
    }
    __syncthreads();

    // reduce the 4 u-group partials in place (bytes can't overflow: <=255 total)
    for (int i = tid; i < NVT * 64; i += 256)
        s_cnt32[i] = s_cnt32[i] + s_cnt32[NVT * 64 + i] +
                     s_cnt32[2 * NVT * 64 + i] + s_cnt32[3 * NVT * 64 + i];
    __syncthreads();

    // write A fragments: counts (0..255) are exact in bf16
    uint32_t* dst = (uint32_t*)g_Af4 + (size_t)b * 4096;
    for (int lin = tid; lin < 4096; lin += 256) {
        int reg  = lin & 3;
        int lane = (lin >> 2) & 31;
        int k    = (lin >> 7) & 1;
        int mt   = lin >> 8;
        int g    = lane >> 2, tig = lane & 3;
        int v    = mt * 16 + (reg & 1) * 8 + g;
        int t0   = k * 16 + (reg >> 1) * 8 + tig * 2;
        int sh   = (v & 3) * 8;
        uint32_t c0 = (s_cnt32[t0 * 64 + (v >> 2)] >> sh) & 255u;
        uint32_t c1 = (s_cnt32[(t0 + 1) * 64 + (v >> 2)] >> sh) & 255u;
        uint32_t u0 = __float_as_uint((float)c0) >> 16;
        uint32_t u1 = __float_as_uint((float)c1) >> 16;
        dst[lin] = u0 | (u1 << 16);
    }
}

// ---------- main kernel: 512 thr, 2 batches/CTA, shared B/gi tables ----------
// smem: sB 64K + gi4 32K + spart 8K + phg 1K = 105 KB -> 2 CTAs/SM (32 warps)
#define SMEM_DYN (65536 + 32768 + 8192 + 1024)

__global__ __launch_bounds__(512, 2)
void dvae_main_kernel(const int* __restrict__ node_types,
                      const float* __restrict__ W1, const float* __restrict__ b1,
                      const float* __restrict__ W2, const float* __restrict__ b2,
                      float* __restrict__ out) {
    extern __shared__ char smem[];
    uint4*  sB4   = (uint4*)smem;                       // [2][64][32] uint4
    __half* gi4   = (__half*)(smem + 65536);            // [128][32][4]
    float*  spart = (float*)(smem + 65536 + 32768);     // [2][8][128]
    float*  phg   = spart + 2 * 8 * 128;                // [2][128]

    const int tid  = threadIdx.x;
    const int wg   = tid >> 8;          // 0/1 -> which batch
    const int wid8 = (tid >> 5) & 7;    // warp within group
    const int lane = tid & 31;
    const int b    = blockIdx.x * 2 + wg;

    // ---- stage B frags + gi4 (uint4 copies, all 512 threads) ----
    for (int i = tid; i < 4096; i += 512) sB4[i] = g_Bf4[i];
    {
        uint4* d2 = (uint4*)gi4;
        for (int i = tid; i < 2048; i += 512) d2[i] = g_gi4[i];
    }
    __syncthreads();

    // ---- A fragments: 2 m-tiles per warp, 2 k-steps ----
    uint4 areg[2][2];
    #pragma unroll
    for (int mt2 = 0; mt2 < 2; mt2++)
        #pragma unroll
        for (int k = 0; k < 2; k++)
            areg[mt2][k] = g_Af4[(size_t)b * 1024 +
                                 (((wid8 * 2 + mt2) * 2 + k) * 32 + lane)];

    const int g    = lane >> 2;
    const int tig  = lane & 3;
    const int odd  = tig & 1;
    const int hbit = tig >> 1;
    const int rowoff = g + (odd << 3);

    int   tv[2];
    bool  excl[2];
    #pragma unroll
    for (int mt2 = 0; mt2 < 2; mt2++) {
        int v = (wid8 * 2 + mt2) * 16 + rowoff;
        tv[mt2]   = node_types[b * NN + v];
        excl[mt2] = (v == 0) || (v == NN - 1);
    }

    float* my_spart = spart + wg * 1024 + wid8 * 128;

    // ---- GEMM + fused epilogue over 64 n-tiles (unroll 1: stay <=64 regs) ----
    #pragma unroll 1
    for (int nt = 0; nt < 64; nt++) {
        float cc[2][4] = {{0.f,0.f,0.f,0.f},{0.f,0.f,0.f,0.f}};
        #pragma unroll
        for (int s = 0; s < 2; s++) {
            uint4 bb = sB4[(s * 64 + nt) * 32 + lane];   // LDS.128
            mma_bf16(cc[0], (const uint32_t*)&areg[0][0], bb.x, bb.y);
            mma_bf16(cc[1], (const uint32_t*)&areg[1][0], bb.x, bb.y);
            mma_bf16(cc[0], (const uint32_t*)&areg[0][1], bb.z, bb.w);
            mma_bf16(cc[1], (const uint32_t*)&areg[1][1], bb.z, bb.w);
        }

        const int h = nt * 2 + hbit;
        float acc = 0.f;
        #pragma unroll
        for (int mt2 = 0; mt2 < 2; mt2++) {
            float* c = cc[mt2];
            // exchange between (r,z) lanes and (n,tb) lanes
            float r1 = __shfl_xor_sync(0xffffffffu, odd ? c[0] : c[2], 1);
            float r2 = __shfl_xor_sync(0xffffffffu, odd ? c[1] : c[3], 1);
            float rin  = odd ? r1 : c[0];
            float zin  = odd ? r2 : c[1];
            float nin  = odd ? c[2] : r1;
            float hpre = odd ? c[3] : r2;
            // one LDS.64: {gi_r, gi_z, gi_n, bhn}
            uint2 gv = *(const uint2*)(gi4 + ((h * 32 + tv[mt2]) << 2));
            float2 f_rz = __half22float2(*(const __half2*)&gv.x);
            float2 f_nb = __half22float2(*(const __half2*)&gv.y);
            float r  = sigmoid_fast(f_rz.x + rin);
            float z  = sigmoid_fast(f_rz.y + zin);
            float nn = tanh_fast(f_nb.x + r * (nin + f_nb.y));
            float Hv = (1.f - z) * nn + z * hpre;
            if (!excl[mt2]) acc += Hv;
        }
        // reduce the 16 lanes sharing this h
        acc += __shfl_xor_sync(0xffffffffu, acc, 1);
        acc += __shfl_xor_sync(0xffffffffu, acc, 4);
        acc += __shfl_xor_sync(0xffffffffu, acc, 8);
        acc += __shfl_xor_sync(0xffffffffu, acc, 16);
        if ((lane & ~2u) == 0)            // lanes 0 (h even) and 2 (h odd)
            my_spart[nt * 2 + (lane >> 1)] = acc;
    }
    __syncthreads();

    // ---- reduce partials, heads (per warp-group / batch) ----
    const int wg_tid = tid & 255;
    if (wg_tid < HS) {
        const float* sp = spart + wg * 1024;
        float s = 0.f;
        #pragma unroll
        for (int w = 0; w < 8; w++) s += sp[w * 128 + wg_tid];
        phg[wg * 128 + wg_tid] = s;
    }
    __syncthreads();

    if (wg_tid < 2 * NZ) {
        const int j = wg_tid & (NZ - 1);
        const float* W  = (wg_tid < NZ) ? W1 : W2;
        const float* bv = (wg_tid < NZ) ? b1 : b2;
        const float* hgp = phg + wg * 128;
        float a0 = bv[j], a1 = 0.f, a2 = 0.f, a3 = 0.f;
        #pragma unroll
        for (int h = 0; h < HS; h += 4) {
            a0 += hgp[h + 0] * W[j * HS + h + 0];
            a1 += hgp[h + 1] * W[j * HS + h + 1];
            a2 += hgp[h + 2] * W[j * HS + h + 2];
            a3 += hgp[h + 3] * W[j * HS + h + 3];
        }
        out[((wg_tid < NZ) ? 0 : BB * NZ) + b * NZ + j] = (a0 + a1) + (a2 + a3);
    }
}

// ---------- launch ----------
extern "C" void kernel_launch(void* const* d_in, const int* in_sizes, int n_in,
                              void* d_out, int out_size) {
    const int*   node_types = (const int*)  d_in[0];
    const int*   adj        = (const int*)  d_in[1];
    const float* W_ih       = (const float*)d_in[2];
    const float* W_hh       = (const float*)d_in[3];
    const float* b_ih       = (const float*)d_in[4];
    const float* b_hh       = (const float*)d_in[5];
    const float* Wg         = (const float*)d_in[6];
    const float* bg         = (const float*)d_in[7];
    const float* Wm         = (const float*)d_in[8];
    const float* W1         = (const float*)d_in[9];
    const float* b1         = (const float*)d_in[10];
    const float* W2         = (const float*)d_in[11];
    const float* b2         = (const float*)d_in[12];
    float* out = (float*)d_out;

    cudaFuncSetAttribute(dvae_main_kernel,
                         cudaFuncAttributeMaxDynamicSharedMemorySize, SMEM_DYN);

    dvae_hist_tables_kernel<<<BB + NVT, 256>>>(node_types, adj,
                                               W_ih, W_hh, b_ih, b_hh,
                                               Wg, bg, Wm);
    dvae_main_kernel<<<BB / 2, 512, SMEM_DYN>>>(node_types,
                                                W1, b1, W2, b2, out);
}

// round 12
// speedup vs baseline: 2.2283x; 1.0746x over previous
#include <cuda_runtime.h>
#include <cuda_fp16.h>
#include <cstdint>

#define BB   512
#define NN   256
#define NVT  32
#define HS   128
#define G3   384
#define NZ   64

// ---------- device globals (no allocation allowed) ----------
// B fragments (fp16 single-pass): [nt(64)][lane(32)] x uint4 = 32 KB
__device__ uint4 g_Bf4[2048];
// gi packed: [h(128)][t(32)] x 4 fp16 {gi_r, gi_z, gi_n, bhn_h} = 32 KB
__device__ uint4 g_gi4[2048];
// A fragments per batch (fp16): [mt(16)][k(2)][lane(32)][reg(4)] = 16 KB/batch
__device__ uint4 g_Af4[(size_t)BB * 1024];

__device__ __forceinline__ float tanh_fast(float x) {
    float y;
    asm("tanh.approx.f32 %0, %1;" : "=f"(y) : "f"(x));
    return y;
}
__device__ __forceinline__ float sigmoid_fast(float x) {
    return fmaf(tanh_fast(0.5f * x), 0.5f, 0.5f);
}
__device__ __forceinline__ void mma_fp16(float* c, const uint32_t* a,
                                         uint32_t b0, uint32_t b1) {
    asm volatile(
        "mma.sync.aligned.m16n8k16.row.col.f32.f16.f16.f32 "
        "{%0,%1,%2,%3}, {%4,%5,%6,%7}, {%8,%9}, {%0,%1,%2,%3};"
        : "+f"(c[0]), "+f"(c[1]), "+f"(c[2]), "+f"(c[3])
        : "r"(a[0]), "r"(a[1]), "r"(a[2]), "r"(a[3]), "r"(b0), "r"(b1));
}

// ---------- fused kernel: blocks [0,512) histogram, [512,544) tables --------
__global__ __launch_bounds__(256, 5)
void dvae_hist_tables_kernel(const int* __restrict__ node_types,
                             const int* __restrict__ adj,
                             const float* __restrict__ W_ih,
                             const float* __restrict__ W_hh,
                             const float* __restrict__ b_ih,
                             const float* __restrict__ b_hh,
                             const float* __restrict__ Wg,
                             const float* __restrict__ bg,
                             const float* __restrict__ Wm) {
    // [grp(4)][t(32)][v4(64)] u32, 4 packed u8 counters each = 32 KB
    __shared__ uint32_t s_cnt32[4 * NVT * 64];
    __shared__ int      s_type[NN];
    __shared__ float    s_tbl[HS];

    const int tid = threadIdx.x;

    if (blockIdx.x >= BB) {
        // ================= tables block =================
        const int t = blockIdx.x - BB;       // 0..31 (type = K index)
        if (tid < HS) {
            float x  = Wg[tid * NVT + t] + bg[tid];
            float sg = __fdividef(1.f, 1.f + __expf(-x));
            s_tbl[tid] = sg * Wm[tid * NVT + t];
        }
        __syncthreads();

        unsigned short* B = (unsigned short*)g_Bf4;
        auto storeB = [&](int j, float val) {
            int nt = j >> 3, nin = j & 7;
            int k = t >> 4, kk = t & 15;
            int tig = (kk & 7) >> 1, half = kk & 1, reg = kk >> 3;
            int lane = nin * 4 + tig;
            int base = ((nt * 32 + lane) * 8) + k * 4 + reg * 2 + half;
            B[base] = __half_as_ushort(__float2half_rn(val));
        };

        for (int g = tid; g < G3; g += 256) {
            const float2* w2 = (const float2*)(W_hh + g * HS);
            const float2* t2 = (const float2*)s_tbl;
            float a0 = 0.f, a1 = 0.f;
            #pragma unroll 8
            for (int i = 0; i < 64; i += 2) {
                float2 w0 = w2[i], w1 = w2[i + 1];
                float2 x0 = t2[i], x1 = t2[i + 1];
                a0 += w0.x * x0.x + w0.y * x0.y;
                a1 += w1.x * x1.x + w1.y * x1.y;
            }
            float acc = a0 + a1;
            storeB((g & 127) * 4 + (g >> 7), acc);   // j = h*4 + c
            // gi packed: [h][t] {r,z,n,bhn}
            __half* GI = (__half*)g_gi4;
            int c = g >> 7, h = g & 127;
            float val = W_ih[g * NVT + t] + b_ih[g] + ((g < 256) ? b_hh[g] : 0.f);
            GI[(h * 32 + t) * 4 + c] = __float2half_rn(val);
        }
        if (tid < HS) {
            storeB(tid * 4 + 3, s_tbl[tid]);   // tbl columns
            __half* GI = (__half*)g_gi4;
            GI[(tid * 32 + t) * 4 + 3] = __float2half_rn(b_hh[256 + tid]);
        }
        return;
    }

    // ================= histogram block (packed-byte counters) =================
    const int b = blockIdx.x;
    s_type[tid] = node_types[b * NN + tid];
    for (int i = tid; i < 4 * NVT * 64; i += 256) s_cnt32[i] = 0;
    __syncthreads();

    {
        const int vg    = tid & 63;      // which v-quad (v = 4*vg .. 4*vg+3)
        const int ug    = tid >> 6;      // u-group 0..3 (private partials)
        const int ubase = ug * 64;
        const int4* arow =
            (const int4*)(adj + ((size_t)b * NN + ubase) * NN) + vg;
        uint32_t* cbase = s_cnt32 + ug * (NVT * 64) + vg;

        #pragma unroll 1
        for (int u = 0; u < 64; u += 4) {
            int4 a0 = __ldg(arow + (u + 0) * 64);
            int4 a1 = __ldg(arow + (u + 1) * 64);
            int4 a2 = __ldg(arow + (u + 2) * 64);
            int4 a3 = __ldg(arow + (u + 3) * 64);
            int t0 = s_type[ubase + u + 0];
            int t1 = s_type[ubase + u + 1];
            int t2 = s_type[ubase + u + 2];
            int t3 = s_type[ubase + u + 3];
            uint32_t p0 = (uint32_t)a0.x | ((uint32_t)a0.y << 8) |
                          ((uint32_t)a0.z << 16) | ((uint32_t)a0.w << 24);
            uint32_t p1 = (uint32_t)a1.x | ((uint32_t)a1.y << 8) |
                          ((uint32_t)a1.z << 16) | ((uint32_t)a1.w << 24);
            uint32_t p2 = (uint32_t)a2.x | ((uint32_t)a2.y << 8) |
                          ((uint32_t)a2.z << 16) | ((uint32_t)a2.w << 24);
            uint32_t p3 = (uint32_t)a3.x | ((uint32_t)a3.y << 8) |
                          ((uint32_t)a3.z << 16) | ((uint32_t)a3.w << 24);
            cbase[t0 * 64] += p0;     // 4 byte-counters per RMW
            cbase[t1 * 64] += p1;
            cbase[t2 * 64] += p2;
            cbase[t3 * 64] += p3;
        }
    }
    __syncthreads();

    // reduce the 4 u-group partials in place (bytes can't overflow: <=255 total)
    for (int i = tid; i < NVT * 64; i += 256)
        s_cnt32[i] = s_cnt32[i] + s_cnt32[NVT * 64 + i] +
                     s_cnt32[2 * NVT * 64 + i] + s_cnt32[3 * NVT * 64 + i];
    __syncthreads();

    // write A fragments: counts (0..255) are exact in fp16
    uint32_t* dst = (uint32_t*)g_Af4 + (size_t)b * 4096;
    for (int lin = tid; lin < 4096; lin += 256) {
        int reg  = lin & 3;
        int lane = (lin >> 2) & 31;
        int k    = (lin >> 7) & 1;
        int mt   = lin >> 8;
        int g    = lane >> 2, tig = lane & 3;
        int v    = mt * 16 + (reg & 1) * 8 + g;
        int t0   = k * 16 + (reg >> 1) * 8 + tig * 2;
        int sh   = (v & 3) * 8;
        uint32_t c0 = (s_cnt32[t0 * 64 + (v >> 2)] >> sh) & 255u;
        uint32_t c1 = (s_cnt32[(t0 + 1) * 64 + (v >> 2)] >> sh) & 255u;
        uint32_t u0 = (uint32_t)__half_as_ushort(__float2half_rn((float)c0));
        uint32_t u1 = (uint32_t)__half_as_ushort(__float2half_rn((float)c1));
        dst[lin] = u0 | (u1 << 16);
    }
}

// ---------- main kernel: 512 thr, 2 batches/CTA, fp16 single-pass GEMM ------
// smem: sB 32K + gi4 32K + spart 8K + phg 1K = 73 KB -> 2 CTAs/SM (32 warps)
#define SMEM_DYN (32768 + 32768 + 8192 + 1024)

__global__ __launch_bounds__(512, 2)
void dvae_main_kernel(const int* __restrict__ node_types,
                      const float* __restrict__ W1, const float* __restrict__ b1,
                      const float* __restrict__ W2, const float* __restrict__ b2,
                      float* __restrict__ out) {
    extern __shared__ char smem[];
    uint4*  sB4   = (uint4*)smem;                       // [64][32] uint4
    __half* gi4   = (__half*)(smem + 32768);            // [128][32][4]
    float*  spart = (float*)(smem + 32768 + 32768);     // [2][8][128]
    float*  phg   = spart + 2 * 8 * 128;                // [2][128]

    const int tid  = threadIdx.x;
    const int wg   = tid >> 8;          // 0/1 -> which batch
    const int wid8 = (tid >> 5) & 7;    // warp within group
    const int lane = tid & 31;
    const int b    = blockIdx.x * 2 + wg;

    // ---- stage B frags + gi4 (uint4 copies, all 512 threads) ----
    for (int i = tid; i < 2048; i += 512) sB4[i] = g_Bf4[i];
    {
        uint4* d2 = (uint4*)gi4;
        for (int i = tid; i < 2048; i += 512) d2[i] = g_gi4[i];
    }
    __syncthreads();

    // ---- A fragments: 2 m-tiles per warp, 2 k-steps ----
    uint4 areg[2][2];
    #pragma unroll
    for (int mt2 = 0; mt2 < 2; mt2++)
        #pragma unroll
        for (int k = 0; k < 2; k++)
            areg[mt2][k] = g_Af4[(size_t)b * 1024 +
                                 (((wid8 * 2 + mt2) * 2 + k) * 32 + lane)];

    const int g    = lane >> 2;
    const int tig  = lane & 3;
    const int odd  = tig & 1;
    const int hbit = tig >> 1;
    const int rowoff = g + (odd << 3);

    int   tv[2];
    bool  excl[2];
    #pragma unroll
    for (int mt2 = 0; mt2 < 2; mt2++) {
        int v = (wid8 * 2 + mt2) * 16 + rowoff;
        tv[mt2]   = node_types[b * NN + v];
        excl[mt2] = (v == 0) || (v == NN - 1);
    }

    float* my_spart = spart + wg * 1024 + wid8 * 128;

    // ---- GEMM + fused epilogue over 64 n-tiles ----
    #pragma unroll 1
    for (int nt = 0; nt < 64; nt++) {
        float cc[2][4] = {{0.f,0.f,0.f,0.f},{0.f,0.f,0.f,0.f}};
        {
            uint4 bb = sB4[nt * 32 + lane];              // one LDS.128
            mma_fp16(cc[0], (const uint32_t*)&areg[0][0], bb.x, bb.y);
            mma_fp16(cc[1], (const uint32_t*)&areg[1][0], bb.x, bb.y);
            mma_fp16(cc[0], (const uint32_t*)&areg[0][1], bb.z, bb.w);
            mma_fp16(cc[1], (const uint32_t*)&areg[1][1], bb.z, bb.w);
        }

        const int h = nt * 2 + hbit;
        float acc = 0.f;
        #pragma unroll
        for (int mt2 = 0; mt2 < 2; mt2++) {
            float* c = cc[mt2];
            // exchange between (r,z) lanes and (n,tb) lanes
            float r1 = __shfl_xor_sync(0xffffffffu, odd ? c[0] : c[2], 1);
            float r2 = __shfl_xor_sync(0xffffffffu, odd ? c[1] : c[3], 1);
            float rin  = odd ? r1 : c[0];
            float zin  = odd ? r2 : c[1];
            float nin  = odd ? c[2] : r1;
            float hpre = odd ? c[3] : r2;
            // one LDS.64: {gi_r, gi_z, gi_n, bhn}
            uint2 gv = *(const uint2*)(gi4 + ((h * 32 + tv[mt2]) << 2));
            float2 f_rz = __half22float2(*(const __half2*)&gv.x);
            float2 f_nb = __half22float2(*(const __half2*)&gv.y);
            float r  = sigmoid_fast(f_rz.x + rin);
            float z  = sigmoid_fast(f_rz.y + zin);
            float nn = tanh_fast(f_nb.x + r * (nin + f_nb.y));
            float Hv = (1.f - z) * nn + z * hpre;
            if (!excl[mt2]) acc += Hv;
        }
        // reduce the 16 lanes sharing this h
        acc += __shfl_xor_sync(0xffffffffu, acc, 1);
        acc += __shfl_xor_sync(0xffffffffu, acc, 4);
        acc += __shfl_xor_sync(0xffffffffu, acc, 8);
        acc += __shfl_xor_sync(0xffffffffu, acc, 16);
        if ((lane & ~2u) == 0)            // lanes 0 (h even) and 2 (h odd)
            my_spart[nt * 2 + (lane >> 1)] = acc;
    }
    __syncthreads();

    // ---- reduce partials, heads (per warp-group / batch) ----
    const int wg_tid = tid & 255;
    if (wg_tid < HS) {
        const float* sp = spart + wg * 1024;
        float s = 0.f;
        #pragma unroll
        for (int w = 0; w < 8; w++) s += sp[w * 128 + wg_tid];
        phg[wg * 128 + wg_tid] = s;
    }
    __syncthreads();

    if (wg_tid < 2 * NZ) {
        const int j = wg_tid & (NZ - 1);
        const float* W  = (wg_tid < NZ) ? W1 : W2;
        const float* bv = (wg_tid < NZ) ? b1 : b2;
        const float* hgp = phg + wg * 128;
        float a0 = bv[j], a1 = 0.f, a2 = 0.f, a3 = 0.f;
        #pragma unroll
        for (int h = 0; h < HS; h += 4) {
            a0 += hgp[h + 0] * W[j * HS + h + 0];
            a1 += hgp[h + 1] * W[j * HS + h + 1];
            a2 += hgp[h + 2] * W[j * HS + h + 2];
            a3 += hgp[h + 3] * W[j * HS + h + 3];
        }
        out[((wg_tid < NZ) ? 0 : BB * NZ) + b * NZ + j] = (a0 + a1) + (a2 + a3);
    }
}

// ---------- launch ----------
extern "C" void kernel_launch(void* const* d_in, const int* in_sizes, int n_in,
                              void* d_out, int out_size) {
    const int*   node_types = (const int*)  d_in[0];
    const int*   adj        = (const int*)  d_in[1];
    const float* W_ih       = (const float*)d_in[2];
    const float* W_hh       = (const float*)d_in[3];
    const float* b_ih       = (const float*)d_in[4];
    const float* b_hh       = (const float*)d_in[5];
    const float* Wg         = (const float*)d_in[6];
    const float* bg         = (const float*)d_in[7];
    const float* Wm         = (const float*)d_in[8];
    const float* W1         = (const float*)d_in[9];
    const float* b1         = (const float*)d_in[10];
    const float* W2         = (const float*)d_in[11];
    const float* b2         = (const float*)d_in[12];
    float* out = (float*)d_out;

    cudaFuncSetAttribute(dvae_main_kernel,
                         cudaFuncAttributeMaxDynamicSharedMemorySize, SMEM_DYN);

    dvae_hist_tables_kernel<<<BB + NVT, 256>>>(node_types, adj,
                                               W_ih, W_hh, b_ih, b_hh,
                                               Wg, bg, Wm);
    dvae_main_kernel<<<BB / 2, 512, SMEM_DYN>>>(node_types,
                                                W1, b1, W2, b2, out);
}

// round 13
// speedup vs baseline: 2.2494x; 1.0095x over previous
#include <cuda_runtime.h>
#include <cuda_fp16.h>
#include <cstdint>

#define BB   512
#define NN   256
#define NVT  32
#define HS   128
#define G3   384
#define NZ   64

// ---------- device globals (no allocation allowed) ----------
// B fragments (fp16 single-pass): [nt(64)][lane(32)] x uint4 = 32 KB
__device__ uint4 g_Bf4[2048];
// gi packed: [h(128)][t(32)] x 4 fp16 {gi_r, gi_z, gi_n, bhn_h} = 32 KB
__device__ uint4 g_gi4[2048];
// A fragments per batch (fp16): [mt(16)][k(2)][lane(32)][reg(4)] = 16 KB/batch
__device__ uint4 g_Af4[(size_t)BB * 1024];

__device__ __forceinline__ float tanh_fast(float x) {
    float y;
    asm("tanh.approx.f32 %0, %1;" : "=f"(y) : "f"(x));
    return y;
}
__device__ __forceinline__ float sigmoid_fast(float x) {
    return fmaf(tanh_fast(0.5f * x), 0.5f, 0.5f);
}
__device__ __forceinline__ void mma_fp16(float* c, const uint32_t* a,
                                         uint32_t b0, uint32_t b1) {
    asm volatile(
        "mma.sync.aligned.m16n8k16.row.col.f32.f16.f16.f32 "
        "{%0,%1,%2,%3}, {%4,%5,%6,%7}, {%8,%9}, {%0,%1,%2,%3};"
        : "+f"(c[0]), "+f"(c[1]), "+f"(c[2]), "+f"(c[3])
        : "r"(a[0]), "r"(a[1]), "r"(a[2]), "r"(a[3]), "r"(b0), "r"(b1));
}

// ---------- fused kernel: blocks [0,512) histogram, [512,544) tables --------
__global__ __launch_bounds__(256, 5)
void dvae_hist_tables_kernel(const int* __restrict__ node_types,
                             const int* __restrict__ adj,
                             const float* __restrict__ W_ih,
                             const float* __restrict__ W_hh,
                             const float* __restrict__ b_ih,
                             const float* __restrict__ b_hh,
                             const float* __restrict__ Wg,
                             const float* __restrict__ bg,
                             const float* __restrict__ Wm) {
    // [grp(4)][t(32)][v4(64)] u32, 4 packed u8 counters each = 32 KB
    __shared__ uint32_t s_cnt32[4 * NVT * 64];
    __shared__ int      s_type[NN];
    __shared__ float    s_tbl[HS];

    const int tid = threadIdx.x;

    if (blockIdx.x >= BB) {
        // ================= tables block =================
        const int t = blockIdx.x - BB;       // 0..31 (type = K index)
        if (tid < HS) {
            float x  = Wg[tid * NVT + t] + bg[tid];
            float sg = __fdividef(1.f, 1.f + __expf(-x));
            s_tbl[tid] = sg * Wm[tid * NVT + t];
        }
        __syncthreads();

        unsigned short* B = (unsigned short*)g_Bf4;
        auto storeB = [&](int j, float val) {
            int nt = j >> 3, nin = j & 7;
            int k = t >> 4, kk = t & 15;
            int tig = (kk & 7) >> 1, half = kk & 1, reg = kk >> 3;
            int lane = nin * 4 + tig;
            int base = ((nt * 32 + lane) * 8) + k * 4 + reg * 2 + half;
            B[base] = __half_as_ushort(__float2half_rn(val));
        };

        for (int g = tid; g < G3; g += 256) {
            const float2* w2 = (const float2*)(W_hh + g * HS);
            const float2* t2 = (const float2*)s_tbl;
            float a0 = 0.f, a1 = 0.f;
            #pragma unroll 8
            for (int i = 0; i < 64; i += 2) {
                float2 w0 = w2[i], w1 = w2[i + 1];
                float2 x0 = t2[i], x1 = t2[i + 1];
                a0 += w0.x * x0.x + w0.y * x0.y;
                a1 += w1.x * x1.x + w1.y * x1.y;
            }
            float acc = a0 + a1;
            storeB((g & 127) * 4 + (g >> 7), acc);   // j = h*4 + c
            // gi packed: [h][t] {r,z,n,bhn}
            __half* GI = (__half*)g_gi4;
            int c = g >> 7, h = g & 127;
            float val = W_ih[g * NVT + t] + b_ih[g] + ((g < 256) ? b_hh[g] : 0.f);
            GI[(h * 32 + t) * 4 + c] = __float2half_rn(val);
        }
        if (tid < HS) {
            storeB(tid * 4 + 3, s_tbl[tid]);   // tbl columns
            __half* GI = (__half*)g_gi4;
            GI[(tid * 32 + t) * 4 + 3] = __float2half_rn(b_hh[256 + tid]);
        }
        return;
    }

    // ================= histogram block (packed-byte counters) =================
    const int b = blockIdx.x;
    s_type[tid] = node_types[b * NN + tid];
    for (int i = tid; i < 4 * NVT * 64; i += 256) s_cnt32[i] = 0;
    __syncthreads();

    {
        const int vg    = tid & 63;      // which v-quad (v = 4*vg .. 4*vg+3)
        const int ug    = tid >> 6;      // u-group 0..3 (private partials)
        const int ubase = ug * 64;
        const int4* arow =
            (const int4*)(adj + ((size_t)b * NN + ubase) * NN) + vg;
        uint32_t* cbase = s_cnt32 + ug * (NVT * 64) + vg;

        #pragma unroll 1
        for (int u = 0; u < 64; u += 4) {
            int4 a0 = __ldg(arow + (u + 0) * 64);
            int4 a1 = __ldg(arow + (u + 1) * 64);
            int4 a2 = __ldg(arow + (u + 2) * 64);
            int4 a3 = __ldg(arow + (u + 3) * 64);
            int t0 = s_type[ubase + u + 0];
            int t1 = s_type[ubase + u + 1];
            int t2 = s_type[ubase + u + 2];
            int t3 = s_type[ubase + u + 3];
            uint32_t p0 = (uint32_t)a0.x | ((uint32_t)a0.y << 8) |
                          ((uint32_t)a0.z << 16) | ((uint32_t)a0.w << 24);
            uint32_t p1 = (uint32_t)a1.x | ((uint32_t)a1.y << 8) |
                          ((uint32_t)a1.z << 16) | ((uint32_t)a1.w << 24);
            uint32_t p2 = (uint32_t)a2.x | ((uint32_t)a2.y << 8) |
                          ((uint32_t)a2.z << 16) | ((uint32_t)a2.w << 24);
            uint32_t p3 = (uint32_t)a3.x | ((uint32_t)a3.y << 8) |
                          ((uint32_t)a3.z << 16) | ((uint32_t)a3.w << 24);
            cbase[t0 * 64] += p0;     // 4 byte-counters per RMW
            cbase[t1 * 64] += p1;
            cbase[t2 * 64] += p2;
            cbase[t3 * 64] += p3;
        }
    }
    __syncthreads();

    // reduce the 4 u-group partials in place (bytes can't overflow: <=255 total)
    for (int i = tid; i < NVT * 64; i += 256)
        s_cnt32[i] = s_cnt32[i] + s_cnt32[NVT * 64 + i] +
                     s_cnt32[2 * NVT * 64 + i] + s_cnt32[3 * NVT * 64 + i];
    __syncthreads();

    // write A fragments: counts (0..255) are exact in fp16
    uint32_t* dst = (uint32_t*)g_Af4 + (size_t)b * 4096;
    for (int lin = tid; lin < 4096; lin += 256) {
        int reg  = lin & 3;
        int lane = (lin >> 2) & 31;
        int k    = (lin >> 7) & 1;
        int mt   = lin >> 8;
        int g    = lane >> 2, tig = lane & 3;
        int v    = mt * 16 + (reg & 1) * 8 + g;
        int t0   = k * 16 + (reg >> 1) * 8 + tig * 2;
        int sh   = (v & 3) * 8;
        uint32_t c0 = (s_cnt32[t0 * 64 + (v >> 2)] >> sh) & 255u;
        uint32_t c1 = (s_cnt32[(t0 + 1) * 64 + (v >> 2)] >> sh) & 255u;
        uint32_t u0 = (uint32_t)__half_as_ushort(__float2half_rn((float)c0));
        uint32_t u1 = (uint32_t)__half_as_ushort(__float2half_rn((float)c1));
        dst[lin] = u0 | (u1 << 16);
    }
}

// ---------- main kernel: 512 thr, 2 batches/CTA, fp16 GEMM, lean epilogue ---
// smem: sB 32K + gi4 32K + spart 32K + phg 1K = 97 KB -> 2 CTAs/SM
#define SMEM_DYN (32768 + 32768 + 32768 + 1024)

__global__ __launch_bounds__(512, 2)
void dvae_main_kernel(const int* __restrict__ node_types,
                      const float* __restrict__ W1, const float* __restrict__ b1,
                      const float* __restrict__ W2, const float* __restrict__ b2,
                      float* __restrict__ out) {
    extern __shared__ char smem[];
    uint4*  sB4   = (uint4*)smem;                       // [64][32] uint4
    __half* gi4   = (__half*)(smem + 32768);            // [128][32][4]
    float*  spart = (float*)(smem + 32768 + 32768);     // [2][8][128][4]
    float*  phg   = (float*)(smem + 32768 + 32768 + 32768); // [2][128]

    const int tid  = threadIdx.x;
    const int wg   = tid >> 8;          // 0/1 -> which batch
    const int wid8 = (tid >> 5) & 7;    // warp within group
    const int lane = tid & 31;
    const int b    = blockIdx.x * 2 + wg;

    // ---- stage B frags + gi4 (uint4 copies, all 512 threads) ----
    for (int i = tid; i < 2048; i += 512) sB4[i] = g_Bf4[i];
    {
        uint4* d2 = (uint4*)gi4;
        for (int i = tid; i < 2048; i += 512) d2[i] = g_gi4[i];
    }
    __syncthreads();

    // ---- A fragments: 2 m-tiles per warp, 2 k-steps ----
    uint4 areg[2][2];
    #pragma unroll
    for (int mt2 = 0; mt2 < 2; mt2++)
        #pragma unroll
        for (int k = 0; k < 2; k++)
            areg[mt2][k] = g_Af4[(size_t)b * 1024 +
                                 (((wid8 * 2 + mt2) * 2 + k) * 32 + lane)];

    const int g    = lane >> 2;
    const int tig  = lane & 3;
    const int odd  = tig & 1;
    const int hbit = tig >> 1;
    const int rowoff = g + (odd << 3);

    int   tv[2];
    bool  excl[2];
    #pragma unroll
    for (int mt2 = 0; mt2 < 2; mt2++) {
        int v = (wid8 * 2 + mt2) * 16 + rowoff;
        tv[mt2]   = node_types[b * NN + v];
        excl[mt2] = (v == 0) || (v == NN - 1);
    }

    // this warp's spart slice: [128 h][4 slots]
    float* my_spart = spart + (wg * 8 + wid8) * 512;
    const bool store_lane = ((lane & 5) == 0);   // lanes 0,2,8,10,16,18,24,26
    const int  slot = lane >> 3;

    // ---- GEMM + fused epilogue over 64 n-tiles ----
    #pragma unroll 1
    for (int nt = 0; nt < 64; nt++) {
        float cc[2][4] = {{0.f,0.f,0.f,0.f},{0.f,0.f,0.f,0.f}};
        {
            uint4 bb = sB4[nt * 32 + lane];              // one LDS.128
            mma_fp16(cc[0], (const uint32_t*)&areg[0][0], bb.x, bb.y);
            mma_fp16(cc[1], (const uint32_t*)&areg[1][0], bb.x, bb.y);
            mma_fp16(cc[0], (const uint32_t*)&areg[0][1], bb.z, bb.w);
            mma_fp16(cc[1], (const uint32_t*)&areg[1][1], bb.z, bb.w);
        }

        const int h = nt * 2 + hbit;
        // packed exchange across the odd-lane pair: 2 shfl instead of 4
        // (values packed fp16 across mt2 — pre-activation O(1), bounded error)
        __half2 p1 = __floats2half2_rn(odd ? cc[0][0] : cc[0][2],
                                       odd ? cc[1][0] : cc[1][2]);
        __half2 p2 = __floats2half2_rn(odd ? cc[0][1] : cc[0][3],
                                       odd ? cc[1][1] : cc[1][3]);
        uint32_t q1 = __shfl_xor_sync(0xffffffffu, *(uint32_t*)&p1, 1);
        uint32_t q2 = __shfl_xor_sync(0xffffffffu, *(uint32_t*)&p2, 1);
        float2 e1 = __half22float2(*(__half2*)&q1);   // .x = mt0, .y = mt1
        float2 e2 = __half22float2(*(__half2*)&q2);

        float acc = 0.f;
        #pragma unroll
        for (int mt2 = 0; mt2 < 2; mt2++) {
            float* c = cc[mt2];
            float r1 = mt2 ? e1.y : e1.x;
            float r2 = mt2 ? e2.y : e2.x;
            float rin  = odd ? r1 : c[0];
            float zin  = odd ? r2 : c[1];
            float nin  = odd ? c[2] : r1;
            float hpre = odd ? c[3] : r2;
            // one LDS.64: {gi_r, gi_z, gi_n, bhn}
            uint2 gv = *(const uint2*)(gi4 + ((h * 32 + tv[mt2]) << 2));
            float2 f_rz = __half22float2(*(const __half2*)&gv.x);
            float2 f_nb = __half22float2(*(const __half2*)&gv.y);
            float r  = sigmoid_fast(f_rz.x + rin);
            float z  = sigmoid_fast(f_rz.y + zin);
            float nn = tanh_fast(f_nb.x + r * (nin + f_nb.y));
            float Hv = (1.f - z) * nn + z * hpre;
            if (!excl[mt2]) acc += Hv;
        }
        // partial reduce: 2 shfl (xor 1 over odd, xor 4 over g-bit0)
        acc += __shfl_xor_sync(0xffffffffu, acc, 1);
        acc += __shfl_xor_sync(0xffffffffu, acc, 4);
        if (store_lane)
            my_spart[h * 4 + slot] = acc;    // conflict-free (8 distinct banks)
    }
    __syncthreads();

    // ---- reduce partials, heads (per warp-group / batch) ----
    const int wg_tid = tid & 255;
    if (wg_tid < HS) {
        const float4* sp = (const float4*)(spart + wg * 8 * 512);
        float s = 0.f;
        #pragma unroll
        for (int w = 0; w < 8; w++) {
            float4 v = sp[w * 128 + wg_tid];
            s += (v.x + v.y) + (v.z + v.w);
        }
        phg[wg * 128 + wg_tid] = s;
    }
    __syncthreads();

    if (wg_tid < 2 * NZ) {
        const int j = wg_tid & (NZ - 1);
        const float* W  = (wg_tid < NZ) ? W1 : W2;
        const float* bv = (wg_tid < NZ) ? b1 : b2;
        const float* hgp = phg + wg * 128;
        float a0 = bv[j], a1 = 0.f, a2 = 0.f, a3 = 0.f;
        #pragma unroll
        for (int h = 0; h < HS; h += 4) {
            a0 += hgp[h + 0] * W[j * HS + h + 0];
            a1 += hgp[h + 1] * W[j * HS + h + 1];
            a2 += hgp[h + 2] * W[j * HS + h + 2];
            a3 += hgp[h + 3] * W[j * HS + h + 3];
        }
        out[((wg_tid < NZ) ? 0 : BB * NZ) + b * NZ + j] = (a0 + a1) + (a2 + a3);
    }
}

// ---------- launch ----------
extern "C" void kernel_launch(void* const* d_in, const int* in_sizes, int n_in,
                              void* d_out, int out_size) {
    const int*   node_types = (const int*)  d_in[0];
    const int*   adj        = (const int*)  d_in[1];
    const float* W_ih       = (const float*)d_in[2];
    const float* W_hh       = (const float*)d_in[3];
    const float* b_ih       = (const float*)d_in[4];
    const float* b_hh       = (const float*)d_in[5];
    const float* Wg         = (const float*)d_in[6];
    const float* bg         = (const float*)d_in[7];
    const float* Wm         = (const float*)d_in[8];
    const float* W1         = (const float*)d_in[9];
    const float* b1         = (const float*)d_in[10];
    const float* W2         = (const float*)d_in[11];
    const float* b2         = (const float*)d_in[12];
    float* out = (float*)d_out;

    cudaFuncSetAttribute(dvae_main_kernel,
                         cudaFuncAttributeMaxDynamicSharedMemorySize, SMEM_DYN);

    dvae_hist_tables_kernel<<<BB + NVT, 256>>>(node_types, adj,
                                               W_ih, W_hh, b_ih, b_hh,
                                               Wg, bg, Wm);
    dvae_main_kernel<<<BB / 2, 512, SMEM_DYN>>>(node_types,
                                                W1, b1, W2, b2, out);
}

// round 14
// speedup vs baseline: 2.2871x; 1.0167x over previous
#include <cuda_runtime.h>
#include <cuda_fp16.h>
#include <cstdint>

#define BB   512
#define NN   256
#define NVT  32
#define HS   128
#define G3   384
#define NZ   64

// ---------- device globals (no allocation allowed) ----------
// B fragments (fp16 single-pass): [nt(64)][lane(32)] x uint4 = 32 KB
__device__ uint4 g_Bf4[2048];
// gi packed: [h(128)][t(32)] x 4 fp16 {gi_r, gi_z, gi_n, bhn_h} = 32 KB
__device__ uint4 g_gi4[2048];
// A fragments per batch (fp16): [mt(16)][k(2)][lane(32)][reg(4)] = 16 KB/batch
__device__ uint4 g_Af4[(size_t)BB * 1024];

__device__ __forceinline__ float tanh_fast(float x) {
    float y;
    asm("tanh.approx.f32 %0, %1;" : "=f"(y) : "f"(x));
    return y;
}
__device__ __forceinline__ float sigmoid_fast(float x) {
    return fmaf(tanh_fast(0.5f * x), 0.5f, 0.5f);
}
__device__ __forceinline__ void mma_fp16(float* c, const uint32_t* a,
                                         uint32_t b0, uint32_t b1) {
    asm volatile(
        "mma.sync.aligned.m16n8k16.row.col.f32.f16.f16.f32 "
        "{%0,%1,%2,%3}, {%4,%5,%6,%7}, {%8,%9}, {%0,%1,%2,%3};"
        : "+f"(c[0]), "+f"(c[1]), "+f"(c[2]), "+f"(c[3])
        : "r"(a[0]), "r"(a[1]), "r"(a[2]), "r"(a[3]), "r"(b0), "r"(b1));
}

// ---------- fused kernel: blocks [0,512) histogram, [512,544) tables --------
__global__ __launch_bounds__(256, 5)
void dvae_hist_tables_kernel(const int* __restrict__ node_types,
                             const int* __restrict__ adj,
                             const float* __restrict__ W_ih,
                             const float* __restrict__ W_hh,
                             const float* __restrict__ b_ih,
                             const float* __restrict__ b_hh,
                             const float* __restrict__ Wg,
                             const float* __restrict__ bg,
                             const float* __restrict__ Wm) {
    // [grp(4)][t(32)][v4(64)] u32, 4 packed u8 counters each = 32 KB
    __shared__ uint32_t s_cnt32[4 * NVT * 64];
    __shared__ int      s_type[NN];
    __shared__ float    s_tbl[HS];

    const int tid = threadIdx.x;

    if (blockIdx.x >= BB) {
        // ================= tables block =================
        const int t = blockIdx.x - BB;       // 0..31 (type = K index)
        if (tid < HS) {
            float x  = Wg[tid * NVT + t] + bg[tid];
            float sg = __fdividef(1.f, 1.f + __expf(-x));
            s_tbl[tid] = sg * Wm[tid * NVT + t];
        }
        __syncthreads();

        unsigned short* B = (unsigned short*)g_Bf4;
        auto storeB = [&](int j, float val) {
            int nt = j >> 3, nin = j & 7;
            int k = t >> 4, kk = t & 15;
            int tig = (kk & 7) >> 1, half = kk & 1, reg = kk >> 3;
            int lane = nin * 4 + tig;
            int base = ((nt * 32 + lane) * 8) + k * 4 + reg * 2 + half;
            B[base] = __half_as_ushort(__float2half_rn(val));
        };

        for (int g = tid; g < G3; g += 256) {
            const float2* w2 = (const float2*)(W_hh + g * HS);
            const float2* t2 = (const float2*)s_tbl;
            float a0 = 0.f, a1 = 0.f;
            #pragma unroll 8
            for (int i = 0; i < 64; i += 2) {
                float2 w0 = w2[i], w1 = w2[i + 1];
                float2 x0 = t2[i], x1 = t2[i + 1];
                a0 += w0.x * x0.x + w0.y * x0.y;
                a1 += w1.x * x1.x + w1.y * x1.y;
            }
            float acc = a0 + a1;
            storeB((g & 127) * 4 + (g >> 7), acc);   // j = h*4 + c
            // gi packed: [h][t] {r,z,n,bhn}
            __half* GI = (__half*)g_gi4;
            int c = g >> 7, h = g & 127;
            float val = W_ih[g * NVT + t] + b_ih[g] + ((g < 256) ? b_hh[g] : 0.f);
            GI[(h * 32 + t) * 4 + c] = __float2half_rn(val);
        }
        if (tid < HS) {
            storeB(tid * 4 + 3, s_tbl[tid]);   // tbl columns
            __half* GI = (__half*)g_gi4;
            GI[(tid * 32 + t) * 4 + 3] = __float2half_rn(b_hh[256 + tid]);
        }
        return;
    }

    // ================= histogram block (packed-byte counters) =================
    const int b = blockIdx.x;
    s_type[tid] = node_types[b * NN + tid];
    for (int i = tid; i < 4 * NVT * 64; i += 256) s_cnt32[i] = 0;
    __syncthreads();

    {
        const int vg    = tid & 63;      // which v-quad (v = 4*vg .. 4*vg+3)
        const int ug    = tid >> 6;      // u-group 0..3 (private partials)
        const int ubase = ug * 64;
        const int4* arow =
            (const int4*)(adj + ((size_t)b * NN + ubase) * NN) + vg;
        uint32_t* cbase = s_cnt32 + ug * (NVT * 64) + vg;

        #pragma unroll 1
        for (int u = 0; u < 64; u += 4) {
            int4 a0 = __ldg(arow + (u + 0) * 64);
            int4 a1 = __ldg(arow + (u + 1) * 64);
            int4 a2 = __ldg(arow + (u + 2) * 64);
            int4 a3 = __ldg(arow + (u + 3) * 64);
            int t0 = s_type[ubase + u + 0];
            int t1 = s_type[ubase + u + 1];
            int t2 = s_type[ubase + u + 2];
            int t3 = s_type[ubase + u + 3];
            uint32_t p0 = (uint32_t)a0.x | ((uint32_t)a0.y << 8) |
                          ((uint32_t)a0.z << 16) | ((uint32_t)a0.w << 24);
            uint32_t p1 = (uint32_t)a1.x | ((uint32_t)a1.y << 8) |
                          ((uint32_t)a1.z << 16) | ((uint32_t)a1.w << 24);
            uint32_t p2 = (uint32_t)a2.x | ((uint32_t)a2.y << 8) |
                          ((uint32_t)a2.z << 16) | ((uint32_t)a2.w << 24);
            uint32_t p3 = (uint32_t)a3.x | ((uint32_t)a3.y << 8) |
                          ((uint32_t)a3.z << 16) | ((uint32_t)a3.w << 24);
            cbase[t0 * 64] += p0;     // 4 byte-counters per RMW
            cbase[t1 * 64] += p1;
            cbase[t2 * 64] += p2;
            cbase[t3 * 64] += p3;
        }
    }
    __syncthreads();

    // reduce the 4 u-group partials in place (bytes can't overflow: <=255 total)
    for (int i = tid; i < NVT * 64; i += 256)
        s_cnt32[i] = s_cnt32[i] + s_cnt32[NVT * 64 + i] +
                     s_cnt32[2 * NVT * 64 + i] + s_cnt32[3 * NVT * 64 + i];
    __syncthreads();

    // write A fragments: counts (0..255) are exact in fp16
    uint32_t* dst = (uint32_t*)g_Af4 + (size_t)b * 4096;
    for (int lin = tid; lin < 4096; lin += 256) {
        int reg  = lin & 3;
        int lane = (lin >> 2) & 31;
        int k    = (lin >> 7) & 1;
        int mt   = lin >> 8;
        int g    = lane >> 2, tig = lane & 3;
        int v    = mt * 16 + (reg & 1) * 8 + g;
        int t0   = k * 16 + (reg >> 1) * 8 + tig * 2;
        int sh   = (v & 3) * 8;
        uint32_t c0 = (s_cnt32[t0 * 64 + (v >> 2)] >> sh) & 255u;
        uint32_t c1 = (s_cnt32[(t0 + 1) * 64 + (v >> 2)] >> sh) & 255u;
        uint32_t u0 = (uint32_t)__half_as_ushort(__float2half_rn((float)c0));
        uint32_t u1 = (uint32_t)__half_as_ushort(__float2half_rn((float)c1));
        dst[lin] = u0 | (u1 << 16);
    }
}

// ---------- main kernel: 512 thr, 2 batches/CTA, 2-way nt pipeline ----------
// smem: sB 32K + gi4 32K + spart 32K + phg 1K = 97 KB -> 2 CTAs/SM
#define SMEM_DYN (32768 + 32768 + 32768 + 1024)

__global__ __launch_bounds__(512, 2)
void dvae_main_kernel(const int* __restrict__ node_types,
                      const float* __restrict__ W1, const float* __restrict__ b1,
                      const float* __restrict__ W2, const float* __restrict__ b2,
                      float* __restrict__ out) {
    extern __shared__ char smem[];
    uint4*  sB4   = (uint4*)smem;                       // [64][32] uint4
    __half* gi4   = (__half*)(smem + 32768);            // [128][32][4]
    float*  spart = (float*)(smem + 32768 + 32768);     // [2][8][128][4]
    float*  phg   = (float*)(smem + 32768 + 32768 + 32768); // [2][128]

    const int tid  = threadIdx.x;
    const int wg   = tid >> 8;          // 0/1 -> which batch
    const int wid8 = (tid >> 5) & 7;    // warp within group
    const int lane = tid & 31;
    const int b    = blockIdx.x * 2 + wg;

    // ---- stage B frags + gi4 (uint4 copies, all 512 threads) ----
    for (int i = tid; i < 2048; i += 512) sB4[i] = g_Bf4[i];
    {
        uint4* d2 = (uint4*)gi4;
        for (int i = tid; i < 2048; i += 512) d2[i] = g_gi4[i];
    }
    __syncthreads();

    // ---- A fragments: 2 m-tiles per warp, 2 k-steps ----
    uint4 areg[2][2];
    #pragma unroll
    for (int mt2 = 0; mt2 < 2; mt2++)
        #pragma unroll
        for (int k = 0; k < 2; k++)
            areg[mt2][k] = g_Af4[(size_t)b * 1024 +
                                 (((wid8 * 2 + mt2) * 2 + k) * 32 + lane)];

    const int g    = lane >> 2;
    const int tig  = lane & 3;
    const int odd  = tig & 1;
    const int hbit = tig >> 1;
    const int rowoff = g + (odd << 3);

    int   tv[2];
    bool  excl[2];
    #pragma unroll
    for (int mt2 = 0; mt2 < 2; mt2++) {
        int v = (wid8 * 2 + mt2) * 16 + rowoff;
        tv[mt2]   = node_types[b * NN + v];
        excl[mt2] = (v == 0) || (v == NN - 1);
    }

    // this warp's spart slice: [128 h][4 slots]
    float* my_spart = spart + (wg * 8 + wid8) * 512;
    const bool store_lane = ((lane & 5) == 0);   // lanes 0,2,8,10,16,18,24,26
    const int  slot = lane >> 3;

    // epilogue for one nt tile (packed exchange + GRU + partial reduce)
    auto epi = [&](int nt, float cc[2][4]) {
        const int h = nt * 2 + hbit;
        __half2 p1 = __floats2half2_rn(odd ? cc[0][0] : cc[0][2],
                                       odd ? cc[1][0] : cc[1][2]);
        __half2 p2 = __floats2half2_rn(odd ? cc[0][1] : cc[0][3],
                                       odd ? cc[1][1] : cc[1][3]);
        uint32_t q1 = __shfl_xor_sync(0xffffffffu, *(uint32_t*)&p1, 1);
        uint32_t q2 = __shfl_xor_sync(0xffffffffu, *(uint32_t*)&p2, 1);
        float2 e1 = __half22float2(*(__half2*)&q1);
        float2 e2 = __half22float2(*(__half2*)&q2);
        float acc = 0.f;
        #pragma unroll
        for (int mt2 = 0; mt2 < 2; mt2++) {
            float* c = cc[mt2];
            float r1 = mt2 ? e1.y : e1.x;
            float r2 = mt2 ? e2.y : e2.x;
            float rin  = odd ? r1 : c[0];
            float zin  = odd ? r2 : c[1];
            float nin  = odd ? c[2] : r1;
            float hpre = odd ? c[3] : r2;
            uint2 gv = *(const uint2*)(gi4 + ((h * 32 + tv[mt2]) << 2));
            float2 f_rz = __half22float2(*(const __half2*)&gv.x);
            float2 f_nb = __half22float2(*(const __half2*)&gv.y);
            float r  = sigmoid_fast(f_rz.x + rin);
            float z  = sigmoid_fast(f_rz.y + zin);
            float nn = tanh_fast(f_nb.x + r * (nin + f_nb.y));
            float Hv = (1.f - z) * nn + z * hpre;
            if (!excl[mt2]) acc += Hv;
        }
        acc += __shfl_xor_sync(0xffffffffu, acc, 1);
        acc += __shfl_xor_sync(0xffffffffu, acc, 4);
        if (store_lane)
            my_spart[h * 4 + slot] = acc;
    };

    // ---- 2-way interleaved nt pipeline: 32 iterations x 2 tiles ----
    #pragma unroll 1
    for (int nt2 = 0; nt2 < 32; nt2++) {
        const int ntA = nt2 * 2, ntB = ntA + 1;
        uint4 bbA = sB4[ntA * 32 + lane];
        uint4 bbB = sB4[ntB * 32 + lane];
        float ccA[2][4] = {{0.f,0.f,0.f,0.f},{0.f,0.f,0.f,0.f}};
        float ccB[2][4] = {{0.f,0.f,0.f,0.f},{0.f,0.f,0.f,0.f}};
        // 8 mma, 4 independent accumulation chains
        mma_fp16(ccA[0], (const uint32_t*)&areg[0][0], bbA.x, bbA.y);
        mma_fp16(ccA[1], (const uint32_t*)&areg[1][0], bbA.x, bbA.y);
        mma_fp16(ccB[0], (const uint32_t*)&areg[0][0], bbB.x, bbB.y);
        mma_fp16(ccB[1], (const uint32_t*)&areg[1][0], bbB.x, bbB.y);
        mma_fp16(ccA[0], (const uint32_t*)&areg[0][1], bbA.z, bbA.w);
        mma_fp16(ccA[1], (const uint32_t*)&areg[1][1], bbA.z, bbA.w);
        mma_fp16(ccB[0], (const uint32_t*)&areg[0][1], bbB.z, bbB.w);
        mma_fp16(ccB[1], (const uint32_t*)&areg[1][1], bbB.z, bbB.w);
        // two independent epilogue chains (ptxas interleaves)
        epi(ntA, ccA);
        epi(ntB, ccB);
    }
    __syncthreads();

    // ---- reduce partials, heads (per warp-group / batch) ----
    const int wg_tid = tid & 255;
    if (wg_tid < HS) {
        const float4* sp = (const float4*)(spart + wg * 8 * 512);
        float s = 0.f;
        #pragma unroll
        for (int w = 0; w < 8; w++) {
            float4 v = sp[w * 128 + wg_tid];
            s += (v.x + v.y) + (v.z + v.w);
        }
        phg[wg * 128 + wg_tid] = s;
    }
    __syncthreads();

    if (wg_tid < 2 * NZ) {
        const int j = wg_tid & (NZ - 1);
        const float* W  = (wg_tid < NZ) ? W1 : W2;
        const float* bv = (wg_tid < NZ) ? b1 : b2;
        const float* hgp = phg + wg * 128;
        float a0 = bv[j], a1 = 0.f, a2 = 0.f, a3 = 0.f;
        #pragma unroll
        for (int h = 0; h < HS; h += 4) {
            a0 += hgp[h + 0] * W[j * HS + h + 0];
            a1 += hgp[h + 1] * W[j * HS + h + 1];
            a2 += hgp[h + 2] * W[j * HS + h + 2];
            a3 += hgp[h + 3] * W[j * HS + h + 3];
        }
        out[((wg_tid < NZ) ? 0 : BB * NZ) + b * NZ + j] = (a0 + a1) + (a2 + a3);
    }
}

// ---------- launch ----------
extern "C" void kernel_launch(void* const* d_in, const int* in_sizes, int n_in,
                              void* d_out, int out_size) {
    const int*   node_types = (const int*)  d_in[0];
    const int*   adj        = (const int*)  d_in[1];
    const float* W_ih       = (const float*)d_in[2];
    const float* W_hh       = (const float*)d_in[3];
    const float* b_ih       = (const float*)d_in[4];
    const float* b_hh       = (const float*)d_in[5];
    const float* Wg         = (const float*)d_in[6];
    const float* bg         = (const float*)d_in[7];
    const float* Wm         = (const float*)d_in[8];
    const float* W1         = (const float*)d_in[9];
    const float* b1         = (const float*)d_in[10];
    const float* W2         = (const float*)d_in[11];
    const float* b2         = (const float*)d_in[12];
    float* out = (float*)d_out;

    cudaFuncSetAttribute(dvae_main_kernel,
                         cudaFuncAttributeMaxDynamicSharedMemorySize, SMEM_DYN);

    dvae_hist_tables_kernel<<<BB + NVT, 256>>>(node_types, adj,
                                               W_ih, W_hh, b_ih, b_hh,
                                               Wg, bg, Wm);
    dvae_main_kernel<<<BB / 2, 512, SMEM_DYN>>>(node_types,
                                                W1, b1, W2, b2, out);
}

// round 15
// speedup vs baseline: 2.3019x; 1.0065x over previous
#include <cuda_runtime.h>
#include <cuda_fp16.h>
#include <cstdint>

#define BB   512
#define NN   256
#define NVT  32
#define HS   128
#define G3   384
#define NZ   64

// ---------- device globals (no allocation allowed) ----------
// B fragments (fp16): [tile(64)][lane(32)] x uint4 = 32 KB
// tile 2p = X (r,z of h in [4p,4p+4)), tile 2p+1 = Y (n,tbl)
__device__ uint4 g_Bf4[2048];
// gi packed: [h(128)][t(32)] x 4 fp16 {gi_r, gi_z, gi_n, bhn_h} = 32 KB
__device__ uint4 g_gi4[2048];
// A fragments per batch (fp16): [mt(16)][k(2)][lane(32)][reg(4)] = 16 KB/batch
__device__ uint4 g_Af4[(size_t)BB * 1024];

__device__ __forceinline__ float tanh_fast(float x) {
    float y;
    asm("tanh.approx.f32 %0, %1;" : "=f"(y) : "f"(x));
    return y;
}
__device__ __forceinline__ float sigmoid_fast(float x) {
    return fmaf(tanh_fast(0.5f * x), 0.5f, 0.5f);
}
__device__ __forceinline__ void mma_fp16(float* c, const uint32_t* a,
                                         uint32_t b0, uint32_t b1) {
    asm volatile(
        "mma.sync.aligned.m16n8k16.row.col.f32.f16.f16.f32 "
        "{%0,%1,%2,%3}, {%4,%5,%6,%7}, {%8,%9}, {%0,%1,%2,%3};"
        : "+f"(c[0]), "+f"(c[1]), "+f"(c[2]), "+f"(c[3])
        : "r"(a[0]), "r"(a[1]), "r"(a[2]), "r"(a[3]), "r"(b0), "r"(b1));
}

// ---------- fused kernel: blocks [0,512) histogram, [512,544) tables --------
__global__ __launch_bounds__(256, 5)
void dvae_hist_tables_kernel(const int* __restrict__ node_types,
                             const int* __restrict__ adj,
                             const float* __restrict__ W_ih,
                             const float* __restrict__ W_hh,
                             const float* __restrict__ b_ih,
                             const float* __restrict__ b_hh,
                             const float* __restrict__ Wg,
                             const float* __restrict__ bg,
                             const float* __restrict__ Wm) {
    // [grp(4)][t(32)][v4(64)] u32, 4 packed u8 counters each = 32 KB
    __shared__ uint32_t s_cnt32[4 * NVT * 64];
    __shared__ int      s_type[NN];
    __shared__ float    s_tbl[HS];

    const int tid = threadIdx.x;

    if (blockIdx.x >= BB) {
        // ================= tables block =================
        const int t = blockIdx.x - BB;       // 0..31 (type = K index)
        if (tid < HS) {
            float x  = Wg[tid * NVT + t] + bg[tid];
            float sg = __fdividef(1.f, 1.f + __expf(-x));
            s_tbl[tid] = sg * Wm[tid * NVT + t];
        }
        __syncthreads();

        unsigned short* B = (unsigned short*)g_Bf4;
        // exchange-free column map: h -> tile pair p=h>>2;
        // X tile (c=r/z) at 2p, Y tile (c=n/tbl) at 2p+1;
        // within-tile column = 2*(h&3) + (c&1)
        auto storeB = [&](int h, int c, float val) {
            int j = ((h >> 2) << 4) | ((c >> 1) << 3) | ((h & 3) << 1) | (c & 1);
            int nt = j >> 3, nin = j & 7;
            int k = t >> 4, kk = t & 15;
            int tig = (kk & 7) >> 1, half = kk & 1, reg = kk >> 3;
            int lane = nin * 4 + tig;
            int base = ((nt * 32 + lane) * 8) + k * 4 + reg * 2 + half;
            B[base] = __half_as_ushort(__float2half_rn(val));
        };

        for (int g = tid; g < G3; g += 256) {
            const float2* w2 = (const float2*)(W_hh + g * HS);
            const float2* t2 = (const float2*)s_tbl;
            float a0 = 0.f, a1 = 0.f;
            #pragma unroll 8
            for (int i = 0; i < 64; i += 2) {
                float2 w0 = w2[i], w1 = w2[i + 1];
                float2 x0 = t2[i], x1 = t2[i + 1];
                a0 += w0.x * x0.x + w0.y * x0.y;
                a1 += w1.x * x1.x + w1.y * x1.y;
            }
            float acc = a0 + a1;
            storeB(g & 127, g >> 7, acc);        // c: 0=r 1=z 2=n
            // gi packed: [h][t] {r,z,n,bhn}
            __half* GI = (__half*)g_gi4;
            int c = g >> 7, h = g & 127;
            float val = W_ih[g * NVT + t] + b_ih[g] + ((g < 256) ? b_hh[g] : 0.f);
            GI[(h * 32 + t) * 4 + c] = __float2half_rn(val);
        }
        if (tid < HS) {
            storeB(tid, 3, s_tbl[tid]);          // tbl columns
            __half* GI = (__half*)g_gi4;
            GI[(tid * 32 + t) * 4 + 3] = __float2half_rn(b_hh[256 + tid]);
        }
        return;
    }

    // ================= histogram block (packed-byte counters) =================
    const int b = blockIdx.x;
    s_type[tid] = node_types[b * NN + tid];
    for (int i = tid; i < 4 * NVT * 64; i += 256) s_cnt32[i] = 0;
    __syncthreads();

    {
        const int vg    = tid & 63;      // which v-quad (v = 4*vg .. 4*vg+3)
        const int ug    = tid >> 6;      // u-group 0..3 (private partials)
        const int ubase = ug * 64;
        const int4* arow =
            (const int4*)(adj + ((size_t)b * NN + ubase) * NN) + vg;
        uint32_t* cbase = s_cnt32 + ug * (NVT * 64) + vg;

        #pragma unroll 1
        for (int u = 0; u < 64; u += 4) {
            int4 a0 = __ldg(arow + (u + 0) * 64);
            int4 a1 = __ldg(arow + (u + 1) * 64);
            int4 a2 = __ldg(arow + (u + 2) * 64);
            int4 a3 = __ldg(arow + (u + 3) * 64);
            int t0 = s_type[ubase + u + 0];
            int t1 = s_type[ubase + u + 1];
            int t2 = s_type[ubase + u + 2];
            int t3 = s_type[ubase + u + 3];
            uint32_t p0 = (uint32_t)a0.x | ((uint32_t)a0.y << 8) |
                          ((uint32_t)a0.z << 16) | ((uint32_t)a0.w << 24);
            uint32_t p1 = (uint32_t)a1.x | ((uint32_t)a1.y << 8) |
                          ((uint32_t)a1.z << 16) | ((uint32_t)a1.w << 24);
            uint32_t p2 = (uint32_t)a2.x | ((uint32_t)a2.y << 8) |
                          ((uint32_t)a2.z << 16) | ((uint32_t)a2.w << 24);
            uint32_t p3 = (uint32_t)a3.x | ((uint32_t)a3.y << 8) |
                          ((uint32_t)a3.z << 16) | ((uint32_t)a3.w << 24);
            cbase[t0 * 64] += p0;     // 4 byte-counters per RMW
            cbase[t1 * 64] += p1;
            cbase[t2 * 64] += p2;
            cbase[t3 * 64] += p3;
        }
    }
    __syncthreads();

    // reduce the 4 u-group partials in place (bytes can't overflow: <=255 total)
    for (int i = tid; i < NVT * 64; i += 256)
        s_cnt32[i] = s_cnt32[i] + s_cnt32[NVT * 64 + i] +
                     s_cnt32[2 * NVT * 64 + i] + s_cnt32[3 * NVT * 64 + i];
    __syncthreads();

    // write A fragments: counts (0..255) are exact in fp16
    uint32_t* dst = (uint32_t*)g_Af4 + (size_t)b * 4096;
    for (int lin = tid; lin < 4096; lin += 256) {
        int reg  = lin & 3;
        int lane = (lin >> 2) & 31;
        int k    = (lin >> 7) & 1;
        int mt   = lin >> 8;
        int g    = lane >> 2, tig = lane & 3;
        int v    = mt * 16 + (reg & 1) * 8 + g;
        int t0   = k * 16 + (reg >> 1) * 8 + tig * 2;
        int sh   = (v & 3) * 8;
        uint32_t c0 = (s_cnt32[t0 * 64 + (v >> 2)] >> sh) & 255u;
        uint32_t c1 = (s_cnt32[(t0 + 1) * 64 + (v >> 2)] >> sh) & 255u;
        uint32_t u0 = (uint32_t)__half_as_ushort(__float2half_rn((float)c0));
        uint32_t u1 = (uint32_t)__half_as_ushort(__float2half_rn((float)c1));
        dst[lin] = u0 | (u1 << 16);
    }
}

// ---------- main kernel: 512 thr, 2 batches/CTA, exchange-free epilogue -----
// smem: sB 32K + gi4 32K + spart 8K + phg 1K = 73 KB -> 2 CTAs/SM
#define SMEM_DYN (32768 + 32768 + 8192 + 1024)

__global__ __launch_bounds__(512, 2)
void dvae_main_kernel(const int* __restrict__ node_types,
                      const float* __restrict__ W1, const float* __restrict__ b1,
                      const float* __restrict__ W2, const float* __restrict__ b2,
                      float* __restrict__ out) {
    extern __shared__ char smem[];
    uint4*  sB4   = (uint4*)smem;                       // [64][32] uint4
    __half* gi4   = (__half*)(smem + 32768);            // [128][32][4]
    float*  spart = (float*)(smem + 32768 + 32768);     // [2][8][128]
    float*  phg   = (float*)(smem + 32768 + 32768 + 8192); // [2][128]

    const int tid  = threadIdx.x;
    const int wg   = tid >> 8;          // 0/1 -> which batch
    const int wid8 = (tid >> 5) & 7;    // warp within group
    const int lane = tid & 31;
    const int b    = blockIdx.x * 2 + wg;

    // ---- stage B frags + gi4 (uint4 copies, all 512 threads) ----
    for (int i = tid; i < 2048; i += 512) sB4[i] = g_Bf4[i];
    {
        uint4* d2 = (uint4*)gi4;
        for (int i = tid; i < 2048; i += 512) d2[i] = g_gi4[i];
    }
    __syncthreads();

    // ---- A fragments: 2 m-tiles per warp, 2 k-steps ----
    uint4 areg[2][2];
    #pragma unroll
    for (int mt2 = 0; mt2 < 2; mt2++)
        #pragma unroll
        for (int k = 0; k < 2; k++)
            areg[mt2][k] = g_Af4[(size_t)b * 1024 +
                                 (((wid8 * 2 + mt2) * 2 + k) * 32 + lane)];

    const int g   = lane >> 2;
    const int tig = lane & 3;

    // each thread covers v rows: (mt, half) -> v = (wid8*2+mt)*16 + g + half*8
    int  tvv[2][2];
    bool excl[2][2];
    #pragma unroll
    for (int mt = 0; mt < 2; mt++)
        #pragma unroll
        for (int hf = 0; hf < 2; hf++) {
            int v = (wid8 * 2 + mt) * 16 + g + hf * 8;
            tvv[mt][hf]  = node_types[b * NN + v];
            excl[mt][hf] = (v == 0) || (v == NN - 1);
        }

    float* spart_w = spart + (wg * 8 + wid8) * 128;

    // ---- GEMM + exchange-free epilogue over 32 tile-pairs ----
    #pragma unroll 1
    for (int p = 0; p < 32; p++) {
        uint4 bbX = sB4[(2 * p)     * 32 + lane];   // (r,z)  columns
        uint4 bbY = sB4[(2 * p + 1) * 32 + lane];   // (n,tbl) columns
        float ccX[2][4] = {{0.f,0.f,0.f,0.f},{0.f,0.f,0.f,0.f}};
        float ccY[2][4] = {{0.f,0.f,0.f,0.f},{0.f,0.f,0.f,0.f}};
        mma_fp16(ccX[0], (const uint32_t*)&areg[0][0], bbX.x, bbX.y);
        mma_fp16(ccX[1], (const uint32_t*)&areg[1][0], bbX.x, bbX.y);
        mma_fp16(ccY[0], (const uint32_t*)&areg[0][0], bbY.x, bbY.y);
        mma_fp16(ccY[1], (const uint32_t*)&areg[1][0], bbY.x, bbY.y);
        mma_fp16(ccX[0], (const uint32_t*)&areg[0][1], bbX.z, bbX.w);
        mma_fp16(ccX[1], (const uint32_t*)&areg[1][1], bbX.z, bbX.w);
        mma_fp16(ccY[0], (const uint32_t*)&areg[0][1], bbY.z, bbY.w);
        mma_fp16(ccY[1], (const uint32_t*)&areg[1][1], bbY.z, bbY.w);

        const int h = p * 4 + tig;     // this thread's h for the whole pair
        float acc = 0.f;
        #pragma unroll
        for (int mt = 0; mt < 2; mt++) {
            #pragma unroll
            for (int hf = 0; hf < 2; hf++) {
                // rows: c[0],c[1] = row g ; c[2],c[3] = row g+8
                float rin  = ccX[mt][hf * 2 + 0];
                float zin  = ccX[mt][hf * 2 + 1];
                float nin  = ccY[mt][hf * 2 + 0];
                float hpre = ccY[mt][hf * 2 + 1];
                uint2 gv = *(const uint2*)(gi4 + ((h * 32 + tvv[mt][hf]) << 2));
                float2 f_rz = __half22float2(*(const __half2*)&gv.x);
                float2 f_nb = __half22float2(*(const __half2*)&gv.y);
                float r  = sigmoid_fast(f_rz.x + rin);
                float z  = sigmoid_fast(f_rz.y + zin);
                float nn = tanh_fast(f_nb.x + r * (nin + f_nb.y));
                float Hv = (1.f - z) * nn + z * hpre;
                if (!excl[mt][hf]) acc += Hv;
            }
        }
        // reduce over the 8 lanes sharing this h (g = 0..7)
        acc += __shfl_xor_sync(0xffffffffu, acc, 4);
        acc += __shfl_xor_sync(0xffffffffu, acc, 8);
        acc += __shfl_xor_sync(0xffffffffu, acc, 16);
        if (lane < 4)
            spart_w[p * 4 + lane] = acc;     // h = p*4 + tig, lane==tig
    }
    __syncthreads();

    // ---- reduce partials, heads (per warp-group / batch) ----
    const int wg_tid = tid & 255;
    if (wg_tid < HS) {
        const float* sp = spart + wg * 8 * 128;
        float s = 0.f;
        #pragma unroll
        for (int w = 0; w < 8; w++) s += sp[w * 128 + wg_tid];
        phg[wg * 128 + wg_tid] = s;
    }
    __syncthreads();

    if (wg_tid < 2 * NZ) {
        const int j = wg_tid & (NZ - 1);
        const float* W  = (wg_tid < NZ) ? W1 : W2;
        const float* bv = (wg_tid < NZ) ? b1 : b2;
        const float* hgp = phg + wg * 128;
        float a0 = bv[j], a1 = 0.f, a2 = 0.f, a3 = 0.f;
        #pragma unroll
        for (int h = 0; h < HS; h += 4) {
            a0 += hgp[h + 0] * W[j * HS + h + 0];
            a1 += hgp[h + 1] * W[j * HS + h + 1];
            a2 += hgp[h + 2] * W[j * HS + h + 2];
            a3 += hgp[h + 3] * W[j * HS + h + 3];
        }
        out[((wg_tid < NZ) ? 0 : BB * NZ) + b * NZ + j] = (a0 + a1) + (a2 + a3);
    }
}

// ---------- launch ----------
extern "C" void kernel_launch(void* const* d_in, const int* in_sizes, int n_in,
                              void* d_out, int out_size) {
    const int*   node_types = (const int*)  d_in[0];
    const int*   adj        = (const int*)  d_in[1];
    const float* W_ih       = (const float*)d_in[2];
    const float* W_hh       = (const float*)d_in[3];
    const float* b_ih       = (const float*)d_in[4];
    const float* b_hh       = (const float*)d_in[5];
    const float* Wg         = (const float*)d_in[6];
    const float* bg         = (const float*)d_in[7];
    const float* Wm         = (const float*)d_in[8];
    const float* W1         = (const float*)d_in[9];
    const float* b1         = (const float*)d_in[10];
    const float* W2         = (const float*)d_in[11];
    const float* b2         = (const float*)d_in[12];
    float* out = (float*)d_out;

    cudaFuncSetAttribute(dvae_main_kernel,
                         cudaFuncAttributeMaxDynamicSharedMemorySize, SMEM_DYN);

    dvae_hist_tables_kernel<<<BB + NVT, 256>>>(node_types, adj,
                                               W_ih, W_hh, b_ih, b_hh,
                                               Wg, bg, Wm);
    dvae_main_kernel<<<BB / 2, 512, SMEM_DYN>>>(node_types,
                                                W1, b1, W2, b2, out);
}